// round 1
// baseline (speedup 1.0000x reference)
#include <cuda_runtime.h>
#include <cuda_bf16.h>
#include <math.h>

// ---------------- problem constants ----------------
#define Bc 4
#define Cc 384
#define Hc 161
#define Wc 161
#define HWc (Hc*Wc)            // 25921
#define NTOK (Bc*HWc)          // 103684
#define Hp 164
#define Wp 176
#define nHw 41
#define nWw 11
#define NWIN (Bc*nHw*nWw)      // 1804
#define Lc 64
#define NHh 8
#define HDd 48
#define NTOKP (NWIN*Lc)        // 115456

// ---------------- scratch (static device, no allocs) ----------------
__device__ float g_xh[(size_t)NTOK*Cc];        // token-major BHWC
__device__ float g_win[(size_t)NTOKP*Cc];      // LN1 windowed (reused as xn2)
__device__ float g_qkv[(size_t)NTOKP*3*Cc];    // qkv (reused as mlp hidden)
__device__ float g_otok[(size_t)NTOK*Cc];      // attention output, token-major
__device__ float g_bns[2688];
__device__ float g_bnt[2688];

// ---------------- BN prep: s = g*rsqrt(rv+eps), t = b - rm*s ----------------
__global__ void bn_prep_kernel(const float* __restrict__ p, int n,
                               float* __restrict__ s, float* __restrict__ t) {
    int i = blockIdx.x * blockDim.x + threadIdx.x;
    if (i < n) {
        float g = p[i], b = p[n + i], rm = p[2*n + i], rv = p[3*n + i];
        float sc = g * rsqrtf(rv + 1e-3f);
        s[i] = sc;
        t[i] = b - rm * sc;
    }
}

// ---------------- transpose BCHW -> B,HW,C ----------------
__global__ void transpose_in_kernel(const float* __restrict__ x, float* __restrict__ xh) {
    __shared__ float tile[32][33];
    int b = blockIdx.z, c0 = blockIdx.y * 32, s0 = blockIdx.x * 32;
    int tx = threadIdx.x, ty = threadIdx.y;
    #pragma unroll
    for (int r = 0; r < 32; r += 8) {
        int c = c0 + ty + r, s = s0 + tx;
        if (s < HWc) tile[ty + r][tx] = x[((size_t)b * Cc + c) * HWc + s];
    }
    __syncthreads();
    #pragma unroll
    for (int r = 0; r < 32; r += 8) {
        int c = c0 + tx, s = s0 + ty + r;
        if (s < HWc) xh[((size_t)b * HWc + s) * Cc + c] = tile[tx][ty + r];
    }
}

// ---------------- transpose B,HW,C -> BCHW ----------------
__global__ void transpose_out_kernel(const float* __restrict__ xh, float* __restrict__ out) {
    __shared__ float tile[32][33];
    int b = blockIdx.z, c0 = blockIdx.y * 32, s0 = blockIdx.x * 32;
    int tx = threadIdx.x, ty = threadIdx.y;
    #pragma unroll
    for (int r = 0; r < 32; r += 8) {
        int s = s0 + ty + r, c = c0 + tx;
        if (s < HWc) tile[ty + r][tx] = xh[((size_t)b * HWc + s) * Cc + c];
    }
    __syncthreads();
    #pragma unroll
    for (int r = 0; r < 32; r += 8) {
        int s = s0 + tx, c = c0 + ty + r;
        if (s < HWc) out[((size_t)b * Cc + c) * HWc + s] = tile[tx][ty + r];
    }
}

// ---------------- block reduce (sum, sumsq) for 128-thread LN ----------------
__device__ __forceinline__ void ln_block_reduce(float& s, float& q, float* sm) {
    #pragma unroll
    for (int o = 16; o; o >>= 1) {
        s += __shfl_down_sync(0xffffffffu, s, o);
        q += __shfl_down_sync(0xffffffffu, q, o);
    }
    int w = threadIdx.x >> 5, lane = threadIdx.x & 31;
    if (!lane) { sm[w] = s; sm[4 + w] = q; }
    __syncthreads();
    s = sm[0] + sm[1] + sm[2] + sm[3];
    q = sm[4] + sm[5] + sm[6] + sm[7];
}

// ---------------- LN1 + window partition (pads -> zeros) ----------------
__global__ void __launch_bounds__(128) ln1_window_kernel(
    const float* __restrict__ xh, const float* __restrict__ g,
    const float* __restrict__ bb, float* __restrict__ win) {
    __shared__ float sm[8];
    int gidx = blockIdx.x;          // wi*64 + l
    int wi = gidx >> 6, l = gidx & 63;
    int b  = wi / (nHw * nWw);
    int r  = wi % (nHw * nWw);
    int hwi = r / nWw, wwi = r % nWw;
    int hp = hwi * 4 + (l >> 4), wp = wwi * 16 + (l & 15);
    float* outp = win + (size_t)gidx * Cc;
    int tid = threadIdx.x;
    if (hp >= Hc || wp >= Wc) {
        outp[tid] = 0.f; outp[tid + 128] = 0.f; outp[tid + 256] = 0.f;
        return;
    }
    const float* row = xh + ((size_t)(b * Hc + hp) * Wc + wp) * Cc;
    float v0 = row[tid], v1 = row[tid + 128], v2 = row[tid + 256];
    float s = v0 + v1 + v2;
    float q = v0*v0 + v1*v1 + v2*v2;
    ln_block_reduce(s, q, sm);
    float mu = s * (1.f / Cc);
    float var = q * (1.f / Cc) - mu * mu;
    float inv = rsqrtf(var + 1e-5f);
    outp[tid]       = (v0 - mu) * inv * g[tid]       + bb[tid];
    outp[tid + 128] = (v1 - mu) * inv * g[tid + 128] + bb[tid + 128];
    outp[tid + 256] = (v2 - mu) * inv * g[tid + 256] + bb[tid + 256];
}

// ---------------- plain LN (token-major) ----------------
__global__ void __launch_bounds__(128) ln2_kernel(
    const float* __restrict__ xh, const float* __restrict__ g,
    const float* __restrict__ bb, float* __restrict__ outbuf) {
    __shared__ float sm[8];
    int tok = blockIdx.x;
    int tid = threadIdx.x;
    const float* row = xh + (size_t)tok * Cc;
    float* outp = outbuf + (size_t)tok * Cc;
    float v0 = row[tid], v1 = row[tid + 128], v2 = row[tid + 256];
    float s = v0 + v1 + v2;
    float q = v0*v0 + v1*v1 + v2*v2;
    ln_block_reduce(s, q, sm);
    float mu = s * (1.f / Cc);
    float var = q * (1.f / Cc) - mu * mu;
    float inv = rsqrtf(var + 1e-5f);
    outp[tid]       = (v0 - mu) * inv * g[tid]       + bb[tid];
    outp[tid + 128] = (v1 - mu) * inv * g[tid + 128] + bb[tid + 128];
    outp[tid + 256] = (v2 - mu) * inv * g[tid + 256] + bb[tid + 256];
}

// ---------------- tiled SGEMM: C[M,N] = epi(A[M,K] @ W[N,K]^T) ----------------
// BM=BN=128, BK=8, 256 threads, 8x8 per thread. Epilogue: BN scale/shift,
// optional SiLU, optional residual add.
template<bool SILU, bool RESID>
__global__ void __launch_bounds__(256) gemm_nt_kernel(
    const float* __restrict__ A, const float* __restrict__ W,
    const float* __restrict__ bns, const float* __restrict__ bnt,
    const float* __restrict__ resid, float* __restrict__ Cout,
    int M, int N, int K) {
    __shared__ float As[8][128];
    __shared__ float Bs[8][128];
    const int m0 = blockIdx.y * 128;
    const int n0 = blockIdx.x * 128;
    const int tid = threadIdx.x;
    const int tx = tid & 15, ty = tid >> 4;
    const int lrow = tid & 127;
    const int lk4  = (tid >> 7) * 4;
    const bool arow_ok = (m0 + lrow) < M;
    const float* Aptr = A + (size_t)(m0 + lrow) * K + lk4;
    const float* Wptr = W + (size_t)(n0 + lrow) * K + lk4;

    float acc[8][8];
    #pragma unroll
    for (int i = 0; i < 8; i++)
        #pragma unroll
        for (int j = 0; j < 8; j++) acc[i][j] = 0.f;

    for (int k0 = 0; k0 < K; k0 += 8) {
        float4 av = arow_ok ? *(const float4*)(Aptr + k0) : make_float4(0.f,0.f,0.f,0.f);
        float4 wv = *(const float4*)(Wptr + k0);
        __syncthreads();
        As[lk4 + 0][lrow] = av.x; As[lk4 + 1][lrow] = av.y;
        As[lk4 + 2][lrow] = av.z; As[lk4 + 3][lrow] = av.w;
        Bs[lk4 + 0][lrow] = wv.x; Bs[lk4 + 1][lrow] = wv.y;
        Bs[lk4 + 2][lrow] = wv.z; Bs[lk4 + 3][lrow] = wv.w;
        __syncthreads();
        #pragma unroll
        for (int kk = 0; kk < 8; kk++) {
            float4 a0 = *(const float4*)&As[kk][ty * 8];
            float4 a1 = *(const float4*)&As[kk][ty * 8 + 4];
            float4 b0 = *(const float4*)&Bs[kk][tx * 8];
            float4 b1 = *(const float4*)&Bs[kk][tx * 8 + 4];
            float a[8] = {a0.x,a0.y,a0.z,a0.w,a1.x,a1.y,a1.z,a1.w};
            float bv[8] = {b0.x,b0.y,b0.z,b0.w,b1.x,b1.y,b1.z,b1.w};
            #pragma unroll
            for (int i = 0; i < 8; i++)
                #pragma unroll
                for (int j = 0; j < 8; j++)
                    acc[i][j] += a[i] * bv[j];
        }
    }

    #pragma unroll
    for (int i = 0; i < 8; i++) {
        int m = m0 + ty * 8 + i;
        if (m < M) {
            size_t rowoff = (size_t)m * N;
            #pragma unroll
            for (int j = 0; j < 8; j++) {
                int n = n0 + tx * 8 + j;
                float v = acc[i][j] * bns[n] + bnt[n];
                if (SILU) v = v / (1.f + __expf(-v));
                if (RESID) v += resid[rowoff + n];
                Cout[rowoff + n] = v;
            }
        }
    }
}

// ---------------- attention: one block per (window, head) ----------------
__global__ void __launch_bounds__(256) attn_kernel(
    const float* __restrict__ qkv, float* __restrict__ otok) {
    __shared__ float qs[64][49];     // q, later reused for v
    __shared__ float ks[64][49];
    __shared__ float S[64][65];
    const int blk = blockIdx.x;
    const int win = blk >> 3, h = blk & 7;
    const int tid = threadIdx.x;
    const float scale = 0.144337567297406f;  // 1/sqrt(48)
    const size_t base = (size_t)win * 64 * 1152 + h * 48;

    for (int idx = tid; idx < 64 * 48; idx += 256) {
        int l = idx / 48, d = idx - l * 48;
        qs[l][d] = qkv[base + (size_t)l * 1152 + d] * scale;
        ks[l][d] = qkv[base + (size_t)l * 1152 + 384 + d];
    }
    __syncthreads();

    const int tx = tid & 15, ty = tid >> 4;
    float acc[4][4];
    #pragma unroll
    for (int i = 0; i < 4; i++)
        #pragma unroll
        for (int j = 0; j < 4; j++) acc[i][j] = 0.f;
    #pragma unroll 8
    for (int d = 0; d < 48; d++) {
        float a[4], bv[4];
        #pragma unroll
        for (int i = 0; i < 4; i++) a[i] = qs[ty * 4 + i][d];
        #pragma unroll
        for (int j = 0; j < 4; j++) bv[j] = ks[tx * 4 + j][d];
        #pragma unroll
        for (int i = 0; i < 4; i++)
            #pragma unroll
            for (int j = 0; j < 4; j++)
                acc[i][j] += a[i] * bv[j];
    }
    #pragma unroll
    for (int i = 0; i < 4; i++)
        #pragma unroll
        for (int j = 0; j < 4; j++)
            S[ty * 4 + i][tx * 4 + j] = acc[i][j];
    __syncthreads();

    // load v into qs (q no longer needed)
    for (int idx = tid; idx < 64 * 48; idx += 256) {
        int l = idx / 48, d = idx - l * 48;
        qs[l][d] = qkv[base + (size_t)l * 1152 + 768 + d];
    }
    // softmax: warp w -> rows w*8 .. w*8+7
    const int wrp = tid >> 5, lane = tid & 31;
    #pragma unroll
    for (int rr = 0; rr < 8; rr++) {
        int r = wrp * 8 + rr;
        float e0 = S[r][lane], e1 = S[r][lane + 32];
        float m = fmaxf(e0, e1);
        #pragma unroll
        for (int o = 16; o; o >>= 1) m = fmaxf(m, __shfl_xor_sync(0xffffffffu, m, o));
        e0 = __expf(e0 - m); e1 = __expf(e1 - m);
        float sum = e0 + e1;
        #pragma unroll
        for (int o = 16; o; o >>= 1) sum += __shfl_xor_sync(0xffffffffu, sum, o);
        float inv = 1.f / sum;
        S[r][lane] = e0 * inv;
        S[r][lane + 32] = e1 * inv;
    }
    __syncthreads();

    // O = P @ V : thread computes rows ty*4..+3, cols tx*3..+2
    float o[4][3];
    #pragma unroll
    for (int i = 0; i < 4; i++)
        #pragma unroll
        for (int c = 0; c < 3; c++) o[i][c] = 0.f;
    #pragma unroll 4
    for (int j = 0; j < 64; j++) {
        float p[4], vv[3];
        #pragma unroll
        for (int i = 0; i < 4; i++) p[i] = S[ty * 4 + i][j];
        #pragma unroll
        for (int c = 0; c < 3; c++) vv[c] = qs[j][tx * 3 + c];
        #pragma unroll
        for (int i = 0; i < 4; i++)
            #pragma unroll
            for (int c = 0; c < 3; c++)
                o[i][c] += p[i] * vv[c];
    }

    const int b  = win / (nHw * nWw);
    const int r2 = win % (nHw * nWw);
    const int hwi = r2 / nWw, wwi = r2 % nWw;
    #pragma unroll
    for (int i = 0; i < 4; i++) {
        int l = ty * 4 + i;
        int hp = hwi * 4 + (l >> 4), wp = wwi * 16 + (l & 15);
        if (hp < Hc && wp < Wc) {
            size_t row = ((size_t)(b * Hc + hp) * Wc + wp) * Cc + h * 48 + tx * 3;
            otok[row + 0] = o[i][0];
            otok[row + 1] = o[i][1];
            otok[row + 2] = o[i][2];
        }
    }
}

// ---------------- host ----------------
extern "C" void kernel_launch(void* const* d_in, const int* in_sizes, int n_in,
                              void* d_out, int out_size) {
    const float* x       = (const float*)d_in[0];
    const float* qkv_w   = (const float*)d_in[1];
    const float* qkv_bn  = (const float*)d_in[2];
    const float* proj_w  = (const float*)d_in[3];
    const float* proj_bn = (const float*)d_in[4];
    const float* n1_g    = (const float*)d_in[5];
    const float* n1_b    = (const float*)d_in[6];
    const float* n2_g    = (const float*)d_in[7];
    const float* n2_b    = (const float*)d_in[8];
    const float* mlp1_w  = (const float*)d_in[9];
    const float* mlp1_bn = (const float*)d_in[10];
    const float* mlp2_w  = (const float*)d_in[11];
    const float* mlp2_bn = (const float*)d_in[12];
    float* out = (float*)d_out;

    float *xh, *win, *qkv, *otok, *bns, *bnt;
    cudaGetSymbolAddress((void**)&xh,   g_xh);
    cudaGetSymbolAddress((void**)&win,  g_win);
    cudaGetSymbolAddress((void**)&qkv,  g_qkv);
    cudaGetSymbolAddress((void**)&otok, g_otok);
    cudaGetSymbolAddress((void**)&bns,  g_bns);
    cudaGetSymbolAddress((void**)&bnt,  g_bnt);

    // BN param prep
    bn_prep_kernel<<<5, 256>>>(qkv_bn, 1152, bns + 0,    bnt + 0);
    bn_prep_kernel<<<2, 256>>>(proj_bn, 384, bns + 1152, bnt + 1152);
    bn_prep_kernel<<<3, 256>>>(mlp1_bn, 768, bns + 1536, bnt + 1536);
    bn_prep_kernel<<<2, 256>>>(mlp2_bn, 384, bns + 2304, bnt + 2304);

    // x (B,C,H,W) -> xh (B,HW,C)
    transpose_in_kernel<<<dim3(811, 12, Bc), dim3(32, 8)>>>(x, xh);

    // LN1 + window partition (pads zeroed)
    ln1_window_kernel<<<NTOKP, 128>>>(xh, n1_g, n1_b, win);

    // qkv = BN(win @ qkv_w^T)
    gemm_nt_kernel<false, false><<<dim3(9, 902), 256>>>(
        win, qkv_w, bns, bnt, nullptr, qkv, NTOKP, 1152, Cc);

    // attention per (window, head) -> otok (token-major, unpadded)
    attn_kernel<<<NWIN * NHh, 256>>>(qkv, otok);

    // xh += BN(otok @ proj_w^T)
    gemm_nt_kernel<false, true><<<dim3(3, 811), 256>>>(
        otok, proj_w, bns + 1152, bnt + 1152, xh, xh, NTOK, Cc, Cc);

    // LN2 -> win (reused as xn2)
    ln2_kernel<<<NTOK, 128>>>(xh, n2_g, n2_b, win);

    // h = silu(BN(xn2 @ mlp1_w^T)) -> qkv buffer reused
    gemm_nt_kernel<true, false><<<dim3(6, 811), 256>>>(
        win, mlp1_w, bns + 1536, bnt + 1536, nullptr, qkv, NTOK, 2 * Cc, Cc);

    // xh += BN(h @ mlp2_w^T)
    gemm_nt_kernel<false, true><<<dim3(3, 811), 256>>>(
        qkv, mlp2_w, bns + 2304, bnt + 2304, xh, xh, NTOK, Cc, 2 * Cc);

    // xh (B,HW,C) -> out (B,C,H,W)
    transpose_out_kernel<<<dim3(811, 12, Bc), dim3(32, 8)>>>(xh, out);
}

// round 3
// speedup vs baseline: 2.0025x; 2.0025x over previous
#include <cuda_runtime.h>
#include <cuda_bf16.h>
#include <math.h>
#include <stdint.h>

// ---------------- problem constants ----------------
#define Bc 4
#define Cc 384
#define Hc 161
#define Wc 161
#define HWc (Hc*Wc)            // 25921
#define NTOK (Bc*HWc)          // 103684
#define nHw 41
#define nWw 11
#define NWIN (Bc*nHw*nWw)      // 1804
#define NHh 8
#define NTOKP (NWIN*64)        // 115456

// ---------------- scratch (static device, no allocs) ----------------
__device__ float g_xh[(size_t)NTOK*Cc];
__device__ float g_win[(size_t)NTOKP*Cc];
__device__ float g_qkv[(size_t)NTOKP*3*Cc];
__device__ float g_otok[(size_t)NTOK*Cc];
__device__ float g_bns[2688];
__device__ float g_bnt[2688];

__device__ __forceinline__ uint32_t smem_u32(const void* p) {
    uint32_t a;
    asm("{ .reg .u64 t; cvta.to.shared.u64 t, %1; cvt.u32.u64 %0, t; }" : "=r"(a) : "l"(p));
    return a;
}

// ---------------- BN prep ----------------
__global__ void bn_prep_kernel(const float* __restrict__ p, int n,
                               float* __restrict__ s, float* __restrict__ t) {
    int i = blockIdx.x * blockDim.x + threadIdx.x;
    if (i < n) {
        float g = p[i], b = p[n + i], rm = p[2*n + i], rv = p[3*n + i];
        float sc = g * rsqrtf(rv + 1e-3f);
        s[i] = sc;
        t[i] = b - rm * sc;
    }
}

// ---------------- transposes ----------------
__global__ void transpose_in_kernel(const float* __restrict__ x, float* __restrict__ xh) {
    __shared__ float tile[32][33];
    int b = blockIdx.z, c0 = blockIdx.y * 32, s0 = blockIdx.x * 32;
    int tx = threadIdx.x, ty = threadIdx.y;
    #pragma unroll
    for (int r = 0; r < 32; r += 8) {
        int c = c0 + ty + r, s = s0 + tx;
        if (s < HWc) tile[ty + r][tx] = x[((size_t)b * Cc + c) * HWc + s];
    }
    __syncthreads();
    #pragma unroll
    for (int r = 0; r < 32; r += 8) {
        int c = c0 + tx, s = s0 + ty + r;
        if (s < HWc) xh[((size_t)b * HWc + s) * Cc + c] = tile[tx][ty + r];
    }
}
__global__ void transpose_out_kernel(const float* __restrict__ xh, float* __restrict__ out) {
    __shared__ float tile[32][33];
    int b = blockIdx.z, c0 = blockIdx.y * 32, s0 = blockIdx.x * 32;
    int tx = threadIdx.x, ty = threadIdx.y;
    #pragma unroll
    for (int r = 0; r < 32; r += 8) {
        int s = s0 + ty + r, c = c0 + tx;
        if (s < HWc) tile[ty + r][tx] = xh[((size_t)b * HWc + s) * Cc + c];
    }
    __syncthreads();
    #pragma unroll
    for (int r = 0; r < 32; r += 8) {
        int s = s0 + tx, c = c0 + ty + r;
        if (s < HWc) out[((size_t)b * Cc + c) * HWc + s] = tile[tx][ty + r];
    }
}

// ---------------- LN reduce ----------------
__device__ __forceinline__ void ln_block_reduce(float& s, float& q, float* sm) {
    #pragma unroll
    for (int o = 16; o; o >>= 1) {
        s += __shfl_down_sync(0xffffffffu, s, o);
        q += __shfl_down_sync(0xffffffffu, q, o);
    }
    int w = threadIdx.x >> 5, lane = threadIdx.x & 31;
    if (!lane) { sm[w] = s; sm[4 + w] = q; }
    __syncthreads();
    s = sm[0] + sm[1] + sm[2] + sm[3];
    q = sm[4] + sm[5] + sm[6] + sm[7];
}

__global__ void __launch_bounds__(128) ln1_window_kernel(
    const float* __restrict__ xh, const float* __restrict__ g,
    const float* __restrict__ bb, float* __restrict__ win) {
    __shared__ float sm[8];
    int gidx = blockIdx.x;
    int wi = gidx >> 6, l = gidx & 63;
    int b  = wi / (nHw * nWw);
    int r  = wi % (nHw * nWw);
    int hwi = r / nWw, wwi = r % nWw;
    int hp = hwi * 4 + (l >> 4), wp = wwi * 16 + (l & 15);
    float* outp = win + (size_t)gidx * Cc;
    int tid = threadIdx.x;
    if (hp >= Hc || wp >= Wc) {
        outp[tid] = 0.f; outp[tid + 128] = 0.f; outp[tid + 256] = 0.f;
        return;
    }
    const float* row = xh + ((size_t)(b * Hc + hp) * Wc + wp) * Cc;
    float v0 = row[tid], v1 = row[tid + 128], v2 = row[tid + 256];
    float s = v0 + v1 + v2;
    float q = v0*v0 + v1*v1 + v2*v2;
    ln_block_reduce(s, q, sm);
    float mu = s * (1.f / Cc);
    float var = q * (1.f / Cc) - mu * mu;
    float inv = rsqrtf(var + 1e-5f);
    outp[tid]       = (v0 - mu) * inv * g[tid]       + bb[tid];
    outp[tid + 128] = (v1 - mu) * inv * g[tid + 128] + bb[tid + 128];
    outp[tid + 256] = (v2 - mu) * inv * g[tid + 256] + bb[tid + 256];
}

__global__ void __launch_bounds__(128) ln2_kernel(
    const float* __restrict__ xh, const float* __restrict__ g,
    const float* __restrict__ bb, float* __restrict__ outbuf) {
    __shared__ float sm[8];
    int tok = blockIdx.x;
    int tid = threadIdx.x;
    const float* row = xh + (size_t)tok * Cc;
    float* outp = outbuf + (size_t)tok * Cc;
    float v0 = row[tid], v1 = row[tid + 128], v2 = row[tid + 256];
    float s = v0 + v1 + v2;
    float q = v0*v0 + v1*v1 + v2*v2;
    ln_block_reduce(s, q, sm);
    float mu = s * (1.f / Cc);
    float var = q * (1.f / Cc) - mu * mu;
    float inv = rsqrtf(var + 1e-5f);
    outp[tid]       = (v0 - mu) * inv * g[tid]       + bb[tid];
    outp[tid + 128] = (v1 - mu) * inv * g[tid + 128] + bb[tid + 128];
    outp[tid + 256] = (v2 - mu) * inv * g[tid + 256] + bb[tid + 256];
}

// ============================================================================
// mma.sync bf16 GEMM (3-term split): C[M,N] = epi(A[M,K] @ W[N,K]^T)
// BM=128 BN=64 BK=16, 256 threads (4x2 warps, warp tile 32x32).
// smem: hi/lo bf16 tiles, padded row stride 24 elems, double buffered.
// ============================================================================
#define PADK 24

__device__ __forceinline__ void ldm_x4(uint32_t* r, uint32_t addr) {
    asm volatile("ldmatrix.sync.aligned.m8n8.x4.shared.b16 {%0,%1,%2,%3}, [%4];"
        : "=r"(r[0]), "=r"(r[1]), "=r"(r[2]), "=r"(r[3]) : "r"(addr));
}
__device__ __forceinline__ void mma_bf16(float* c, const uint32_t* a, const uint32_t* b) {
    asm volatile("mma.sync.aligned.m16n8k16.row.col.f32.bf16.bf16.f32 "
        "{%0,%1,%2,%3}, {%4,%5,%6,%7}, {%8,%9}, {%0,%1,%2,%3};"
        : "+f"(c[0]), "+f"(c[1]), "+f"(c[2]), "+f"(c[3])
        : "r"(a[0]), "r"(a[1]), "r"(a[2]), "r"(a[3]), "r"(b[0]), "r"(b[1]));
}

template<bool SILU, bool RESID>
__global__ void __launch_bounds__(256) gemm_mma_kernel(
    const float* __restrict__ A, const float* __restrict__ W,
    const float* __restrict__ bns, const float* __restrict__ bnt,
    const float* __restrict__ resid, float* __restrict__ Cout,
    int M, int N, int K) {
    __shared__ __align__(16) __nv_bfloat16 sA[2][2][128][PADK];  // [stage][hi/lo]
    __shared__ __align__(16) __nv_bfloat16 sW[2][2][64][PADK];

    const int tid = threadIdx.x;
    const int wid = tid >> 5, lane = tid & 31;
    const int m0 = blockIdx.y * 128, n0 = blockIdx.x * 64;
    const int m_off = (wid & 3) * 32, n_off = (wid >> 2) * 32;

    // load indices
    const int arow = tid >> 1, ac0 = (tid & 1) * 8;
    const int wrow = tid >> 2, wc0 = (tid & 3) * 4;
    const bool aok = (m0 + arow) < M;
    const float* Ap = A + (size_t)(m0 + arow) * K + ac0;
    const float* Wp = W + (size_t)(n0 + wrow) * K + wc0;

    float acc[2][4][4];
    #pragma unroll
    for (int i = 0; i < 2; i++)
        #pragma unroll
        for (int j = 0; j < 4; j++)
            #pragma unroll
            for (int e = 0; e < 4; e++) acc[i][j][e] = 0.f;

    const int nk = K >> 4;
    float4 pa0, pa1, pw;
    // prefetch chunk 0
    pa0 = aok ? *(const float4*)(Ap)     : make_float4(0,0,0,0);
    pa1 = aok ? *(const float4*)(Ap + 4) : make_float4(0,0,0,0);
    pw  = *(const float4*)(Wp);

    for (int k = 0; k < nk; k++) {
        const int st = k & 1;
        // convert + store prefetched chunk into stage st
        {
            float fa[8] = {pa0.x,pa0.y,pa0.z,pa0.w,pa1.x,pa1.y,pa1.z,pa1.w};
            uint32_t hu[4], lu[4];
            #pragma unroll
            for (int t = 0; t < 4; t++) {
                __nv_bfloat162 h = __floats2bfloat162_rn(fa[2*t], fa[2*t+1]);
                float lx = fa[2*t]   - __low2float(h);
                float ly = fa[2*t+1] - __high2float(h);
                __nv_bfloat162 l2 = __floats2bfloat162_rn(lx, ly);
                hu[t] = *reinterpret_cast<uint32_t*>(&h);
                lu[t] = *reinterpret_cast<uint32_t*>(&l2);
            }
            *(uint4*)&sA[st][0][arow][ac0] = make_uint4(hu[0],hu[1],hu[2],hu[3]);
            *(uint4*)&sA[st][1][arow][ac0] = make_uint4(lu[0],lu[1],lu[2],lu[3]);
            float fw[4] = {pw.x,pw.y,pw.z,pw.w};
            uint32_t whu[2], wlu[2];
            #pragma unroll
            for (int t = 0; t < 2; t++) {
                __nv_bfloat162 h = __floats2bfloat162_rn(fw[2*t], fw[2*t+1]);
                float lx = fw[2*t]   - __low2float(h);
                float ly = fw[2*t+1] - __high2float(h);
                __nv_bfloat162 l2 = __floats2bfloat162_rn(lx, ly);
                whu[t] = *reinterpret_cast<uint32_t*>(&h);
                wlu[t] = *reinterpret_cast<uint32_t*>(&l2);
            }
            *(uint2*)&sW[st][0][wrow][wc0] = make_uint2(whu[0], whu[1]);
            *(uint2*)&sW[st][1][wrow][wc0] = make_uint2(wlu[0], wlu[1]);
        }
        __syncthreads();

        // prefetch next chunk (latency hidden by MMA below)
        if (k + 1 < nk) {
            const float* ap = Ap + (k + 1) * 16;
            const float* wp2 = Wp + (k + 1) * 16;
            pa0 = aok ? *(const float4*)(ap)     : make_float4(0,0,0,0);
            pa1 = aok ? *(const float4*)(ap + 4) : make_float4(0,0,0,0);
            pw  = *(const float4*)(wp2);
        }

        // fragment loads
        uint32_t ah[2][4], al[2][4], bh[4][2], bl[4][2];
        {
            const int arow_f = (lane & 15), acol_f = (lane >> 4) * 8;
            #pragma unroll
            for (int mt = 0; mt < 2; mt++) {
                ldm_x4(ah[mt], smem_u32(&sA[st][0][m_off + mt*16 + arow_f][acol_f]));
                ldm_x4(al[mt], smem_u32(&sA[st][1][m_off + mt*16 + arow_f][acol_f]));
            }
            #pragma unroll
            for (int np = 0; np < 2; np++) {
                uint32_t r[4];
                ldm_x4(r, smem_u32(&sW[st][0][n_off + np*16 + arow_f][acol_f]));
                bh[2*np][0] = r[0]; bh[2*np][1] = r[2];
                bh[2*np+1][0] = r[1]; bh[2*np+1][1] = r[3];
                ldm_x4(r, smem_u32(&sW[st][1][n_off + np*16 + arow_f][acol_f]));
                bl[2*np][0] = r[0]; bl[2*np][1] = r[2];
                bl[2*np+1][0] = r[1]; bl[2*np+1][1] = r[3];
            }
        }
        // 3-term MMAs
        #pragma unroll
        for (int mt = 0; mt < 2; mt++)
            #pragma unroll
            for (int nt = 0; nt < 4; nt++)
                mma_bf16(acc[mt][nt], ah[mt], bh[nt]);
        #pragma unroll
        for (int mt = 0; mt < 2; mt++)
            #pragma unroll
            for (int nt = 0; nt < 4; nt++)
                mma_bf16(acc[mt][nt], al[mt], bh[nt]);
        #pragma unroll
        for (int mt = 0; mt < 2; mt++)
            #pragma unroll
            for (int nt = 0; nt < 4; nt++)
                mma_bf16(acc[mt][nt], ah[mt], bl[nt]);
        __syncthreads();
    }

    // epilogue
    const int erow = lane >> 2, ecol = (lane & 3) * 2;
    #pragma unroll
    for (int mt = 0; mt < 2; mt++) {
        #pragma unroll
        for (int half = 0; half < 2; half++) {
            int m = m0 + m_off + mt * 16 + erow + half * 8;
            if (m < M) {
                size_t rowoff = (size_t)m * N;
                #pragma unroll
                for (int nt = 0; nt < 4; nt++) {
                    int n = n0 + n_off + nt * 8 + ecol;
                    float v0 = acc[mt][nt][half*2]     * bns[n]     + bnt[n];
                    float v1 = acc[mt][nt][half*2 + 1] * bns[n + 1] + bnt[n + 1];
                    if (SILU) {
                        v0 = v0 / (1.f + __expf(-v0));
                        v1 = v1 / (1.f + __expf(-v1));
                    }
                    if (RESID) {
                        float2 rr = *(const float2*)(resid + rowoff + n);
                        v0 += rr.x; v1 += rr.y;
                    }
                    *(float2*)(Cout + rowoff + n) = make_float2(v0, v1);
                }
            }
        }
    }
}

// ---------------- attention: one block per (window, head) ----------------
__global__ void __launch_bounds__(256) attn_kernel(
    const float* __restrict__ qkv, float* __restrict__ otok) {
    __shared__ float qs[64][49];
    __shared__ float ks[64][49];
    __shared__ float S[64][65];
    const int blk = blockIdx.x;
    const int win = blk >> 3, h = blk & 7;
    const int tid = threadIdx.x;
    const float scale = 0.144337567297406f;
    const size_t base = (size_t)win * 64 * 1152 + h * 48;

    for (int idx = tid; idx < 64 * 48; idx += 256) {
        int l = idx / 48, d = idx - l * 48;
        qs[l][d] = qkv[base + (size_t)l * 1152 + d] * scale;
        ks[l][d] = qkv[base + (size_t)l * 1152 + 384 + d];
    }
    __syncthreads();

    const int tx = tid & 15, ty = tid >> 4;
    float acc[4][4];
    #pragma unroll
    for (int i = 0; i < 4; i++)
        #pragma unroll
        for (int j = 0; j < 4; j++) acc[i][j] = 0.f;
    #pragma unroll 8
    for (int d = 0; d < 48; d++) {
        float a[4], bv[4];
        #pragma unroll
        for (int i = 0; i < 4; i++) a[i] = qs[ty * 4 + i][d];
        #pragma unroll
        for (int j = 0; j < 4; j++) bv[j] = ks[tx * 4 + j][d];
        #pragma unroll
        for (int i = 0; i < 4; i++)
            #pragma unroll
            for (int j = 0; j < 4; j++)
                acc[i][j] += a[i] * bv[j];
    }
    #pragma unroll
    for (int i = 0; i < 4; i++)
        #pragma unroll
        for (int j = 0; j < 4; j++)
            S[ty * 4 + i][tx * 4 + j] = acc[i][j];
    __syncthreads();

    for (int idx = tid; idx < 64 * 48; idx += 256) {
        int l = idx / 48, d = idx - l * 48;
        qs[l][d] = qkv[base + (size_t)l * 1152 + 768 + d];
    }
    const int wrp = tid >> 5, lane = tid & 31;
    #pragma unroll
    for (int rr = 0; rr < 8; rr++) {
        int rw = wrp * 8 + rr;
        float e0 = S[rw][lane], e1 = S[rw][lane + 32];
        float mx = fmaxf(e0, e1);
        #pragma unroll
        for (int o = 16; o; o >>= 1) mx = fmaxf(mx, __shfl_xor_sync(0xffffffffu, mx, o));
        e0 = __expf(e0 - mx); e1 = __expf(e1 - mx);
        float sum = e0 + e1;
        #pragma unroll
        for (int o = 16; o; o >>= 1) sum += __shfl_xor_sync(0xffffffffu, sum, o);
        float inv = 1.f / sum;
        S[rw][lane] = e0 * inv;
        S[rw][lane + 32] = e1 * inv;
    }
    __syncthreads();

    float o[4][3];
    #pragma unroll
    for (int i = 0; i < 4; i++)
        #pragma unroll
        for (int c = 0; c < 3; c++) o[i][c] = 0.f;
    #pragma unroll 4
    for (int j = 0; j < 64; j++) {
        float p[4], vv[3];
        #pragma unroll
        for (int i = 0; i < 4; i++) p[i] = S[ty * 4 + i][j];
        #pragma unroll
        for (int c = 0; c < 3; c++) vv[c] = qs[j][tx * 3 + c];
        #pragma unroll
        for (int i = 0; i < 4; i++)
            #pragma unroll
            for (int c = 0; c < 3; c++)
                o[i][c] += p[i] * vv[c];
    }

    const int b  = win / (nHw * nWw);
    const int r2 = win % (nHw * nWw);
    const int hwi = r2 / nWw, wwi = r2 % nWw;
    #pragma unroll
    for (int i = 0; i < 4; i++) {
        int l = ty * 4 + i;
        int hp = hwi * 4 + (l >> 4), wp = wwi * 16 + (l & 15);
        if (hp < Hc && wp < Wc) {
            size_t row = ((size_t)(b * Hc + hp) * Wc + wp) * Cc + h * 48 + tx * 3;
            otok[row + 0] = o[i][0];
            otok[row + 1] = o[i][1];
            otok[row + 2] = o[i][2];
        }
    }
}

// ---------------- host ----------------
extern "C" void kernel_launch(void* const* d_in, const int* in_sizes, int n_in,
                              void* d_out, int out_size) {
    const float* x       = (const float*)d_in[0];
    const float* qkv_w   = (const float*)d_in[1];
    const float* qkv_bn  = (const float*)d_in[2];
    const float* proj_w  = (const float*)d_in[3];
    const float* proj_bn = (const float*)d_in[4];
    const float* n1_g    = (const float*)d_in[5];
    const float* n1_b    = (const float*)d_in[6];
    const float* n2_g    = (const float*)d_in[7];
    const float* n2_b    = (const float*)d_in[8];
    const float* mlp1_w  = (const float*)d_in[9];
    const float* mlp1_bn = (const float*)d_in[10];
    const float* mlp2_w  = (const float*)d_in[11];
    const float* mlp2_bn = (const float*)d_in[12];
    float* out = (float*)d_out;

    float *xh, *win, *qkv, *otok, *bns, *bnt;
    cudaGetSymbolAddress((void**)&xh,   g_xh);
    cudaGetSymbolAddress((void**)&win,  g_win);
    cudaGetSymbolAddress((void**)&qkv,  g_qkv);
    cudaGetSymbolAddress((void**)&otok, g_otok);
    cudaGetSymbolAddress((void**)&bns,  g_bns);
    cudaGetSymbolAddress((void**)&bnt,  g_bnt);

    bn_prep_kernel<<<5, 256>>>(qkv_bn, 1152, bns + 0,    bnt + 0);
    bn_prep_kernel<<<2, 256>>>(proj_bn, 384, bns + 1152, bnt + 1152);
    bn_prep_kernel<<<3, 256>>>(mlp1_bn, 768, bns + 1536, bnt + 1536);
    bn_prep_kernel<<<2, 256>>>(mlp2_bn, 384, bns + 2304, bnt + 2304);

    transpose_in_kernel<<<dim3(811, 12, Bc), dim3(32, 8)>>>(x, xh);
    ln1_window_kernel<<<NTOKP, 128>>>(xh, n1_g, n1_b, win);

    // qkv = BN(win @ qkv_w^T)   M=115456, N=1152, K=384
    gemm_mma_kernel<false,false><<<dim3(18, 902), 256>>>(
        win, qkv_w, bns, bnt, nullptr, qkv, NTOKP, 1152, Cc);

    attn_kernel<<<NWIN * NHh, 256>>>(qkv, otok);

    // xh += BN(otok @ proj_w^T)  M=103684, N=384, K=384
    gemm_mma_kernel<false,true><<<dim3(6, 811), 256>>>(
        otok, proj_w, bns + 1152, bnt + 1152, xh, xh, NTOK, Cc, Cc);

    ln2_kernel<<<NTOK, 128>>>(xh, n2_g, n2_b, win);

    // h = silu(BN(xn2 @ mlp1_w^T))  M=103684, N=768, K=384
    gemm_mma_kernel<true,false><<<dim3(12, 811), 256>>>(
        win, mlp1_w, bns + 1536, bnt + 1536, nullptr, qkv, NTOK, 2 * Cc, Cc);

    // xh += BN(h @ mlp2_w^T)  M=103684, N=384, K=768
    gemm_mma_kernel<false,true><<<dim3(6, 811), 256>>>(
        qkv, mlp2_w, bns + 2304, bnt + 2304, xh, xh, NTOK, Cc, 2 * Cc);

    transpose_out_kernel<<<dim3(811, 12, Bc), dim3(32, 8)>>>(xh, out);
}

// round 5
// speedup vs baseline: 2.1250x; 1.0612x over previous
#include <cuda_runtime.h>
#include <cuda_bf16.h>
#include <math.h>
#include <stdint.h>

// ---------------- problem constants ----------------
#define Bc 4
#define Cc 384
#define Hc 161
#define Wc 161
#define HWc (Hc*Wc)            // 25921
#define NTOK (Bc*HWc)          // 103684
#define nHw 41
#define nWw 11
#define NWIN (Bc*nHw*nWw)      // 1804
#define NHh 8
#define NTOKP (NWIN*64)        // 115456

// ---------------- scratch (static device, no allocs) ----------------
__device__ float g_xh[(size_t)NTOK*Cc];
__device__ float g_qkv[(size_t)NTOKP*3*Cc];
__device__ __nv_bfloat16 g_act_h[(size_t)NTOKP*Cc];
__device__ __nv_bfloat16 g_act_l[(size_t)NTOKP*Cc];
__device__ __nv_bfloat16 g_ot_h[(size_t)NTOK*Cc];
__device__ __nv_bfloat16 g_ot_l[(size_t)NTOK*Cc];
__device__ __nv_bfloat16 g_h_h[(size_t)NTOK*2*Cc];
__device__ __nv_bfloat16 g_h_l[(size_t)NTOK*2*Cc];
__device__ __nv_bfloat16 g_wq_h[1152*384], g_wq_l[1152*384];
__device__ __nv_bfloat16 g_wp_h[384*384],  g_wp_l[384*384];
__device__ __nv_bfloat16 g_w1_h[768*384],  g_w1_l[768*384];
__device__ __nv_bfloat16 g_w2_h[384*768],  g_w2_l[384*768];
__device__ float g_bns[2688];
__device__ float g_bnt[2688];

__device__ __forceinline__ uint32_t smem_u32(const void* p) {
    uint32_t a;
    asm("{ .reg .u64 t; cvta.to.shared.u64 t, %1; cvt.u32.u64 %0, t; }" : "=r"(a) : "l"(p));
    return a;
}

__device__ __forceinline__ void split_store(float v0, float v1,
                                            __nv_bfloat16* ph, __nv_bfloat16* pl) {
    __nv_bfloat162 h2 = __floats2bfloat162_rn(v0, v1);
    float l0 = v0 - __low2float(h2);
    float l1 = v1 - __high2float(h2);
    __nv_bfloat162 l2 = __floats2bfloat162_rn(l0, l1);
    *reinterpret_cast<__nv_bfloat162*>(ph) = h2;
    *reinterpret_cast<__nv_bfloat162*>(pl) = l2;
}

// ---------------- BN prep ----------------
__global__ void bn_prep_kernel(const float* __restrict__ p, int n,
                               float* __restrict__ s, float* __restrict__ t) {
    int i = blockIdx.x * blockDim.x + threadIdx.x;
    if (i < n) {
        float g = p[i], b = p[n + i], rm = p[2*n + i], rv = p[3*n + i];
        float sc = g * rsqrtf(rv + 1e-3f);
        s[i] = sc;
        t[i] = b - rm * sc;
    }
}

// ---------------- weight split ----------------
__global__ void wsplit_kernel(const float* __restrict__ w, int n,
                              __nv_bfloat16* __restrict__ wh, __nv_bfloat16* __restrict__ wl) {
    int i = (blockIdx.x * blockDim.x + threadIdx.x) * 2;
    if (i < n) {
        float v0 = w[i], v1 = w[i + 1];
        split_store(v0, v1, wh + i, wl + i);
    }
}

// ---------------- transposes ----------------
__global__ void transpose_in_kernel(const float* __restrict__ x, float* __restrict__ xh) {
    __shared__ float tile[32][33];
    int b = blockIdx.z, c0 = blockIdx.y * 32, s0 = blockIdx.x * 32;
    int tx = threadIdx.x, ty = threadIdx.y;
    #pragma unroll
    for (int r = 0; r < 32; r += 8) {
        int c = c0 + ty + r, s = s0 + tx;
        if (s < HWc) tile[ty + r][tx] = x[((size_t)b * Cc + c) * HWc + s];
    }
    __syncthreads();
    #pragma unroll
    for (int r = 0; r < 32; r += 8) {
        int c = c0 + tx, s = s0 + ty + r;
        if (s < HWc) xh[((size_t)b * HWc + s) * Cc + c] = tile[tx][ty + r];
    }
}
__global__ void transpose_out_kernel(const float* __restrict__ xh, float* __restrict__ out) {
    __shared__ float tile[32][33];
    int b = blockIdx.z, c0 = blockIdx.y * 32, s0 = blockIdx.x * 32;
    int tx = threadIdx.x, ty = threadIdx.y;
    #pragma unroll
    for (int r = 0; r < 32; r += 8) {
        int s = s0 + ty + r, c = c0 + tx;
        if (s < HWc) tile[ty + r][tx] = xh[((size_t)b * HWc + s) * Cc + c];
    }
    __syncthreads();
    #pragma unroll
    for (int r = 0; r < 32; r += 8) {
        int s = s0 + tx, c = c0 + ty + r;
        if (s < HWc) out[((size_t)b * Cc + c) * HWc + s] = tile[tx][ty + r];
    }
}

// ---------------- LN reduce ----------------
__device__ __forceinline__ void ln_block_reduce(float& s, float& q, float* sm) {
    #pragma unroll
    for (int o = 16; o; o >>= 1) {
        s += __shfl_down_sync(0xffffffffu, s, o);
        q += __shfl_down_sync(0xffffffffu, q, o);
    }
    int w = threadIdx.x >> 5, lane = threadIdx.x & 31;
    if (!lane) { sm[w] = s; sm[4 + w] = q; }
    __syncthreads();
    s = sm[0] + sm[1] + sm[2] + sm[3];
    q = sm[4] + sm[5] + sm[6] + sm[7];
}

// LN1 + window partition -> split bf16
__global__ void __launch_bounds__(128) ln1_window_kernel(
    const float* __restrict__ xh, const float* __restrict__ g,
    const float* __restrict__ bb,
    __nv_bfloat16* __restrict__ oh, __nv_bfloat16* __restrict__ ol) {
    __shared__ float sm[8];
    int gidx = blockIdx.x;
    int wi = gidx >> 6, l = gidx & 63;
    int b  = wi / (nHw * nWw);
    int r  = wi % (nHw * nWw);
    int hwi = r / nWw, wwi = r % nWw;
    int hp = hwi * 4 + (l >> 4), wp = wwi * 16 + (l & 15);
    size_t obase = (size_t)gidx * Cc;
    int tid = threadIdx.x;
    if (hp >= Hc || wp >= Wc) {
        __nv_bfloat16 z = __float2bfloat16(0.f);
        #pragma unroll
        for (int j = 0; j < 3; j++) {
            oh[obase + tid + j*128] = z;
            ol[obase + tid + j*128] = z;
        }
        return;
    }
    const float* row = xh + ((size_t)(b * Hc + hp) * Wc + wp) * Cc;
    float v0 = row[tid], v1 = row[tid + 128], v2 = row[tid + 256];
    float s = v0 + v1 + v2;
    float q = v0*v0 + v1*v1 + v2*v2;
    ln_block_reduce(s, q, sm);
    float mu = s * (1.f / Cc);
    float var = q * (1.f / Cc) - mu * mu;
    float inv = rsqrtf(var + 1e-5f);
    float o0 = (v0 - mu) * inv * g[tid]       + bb[tid];
    float o1 = (v1 - mu) * inv * g[tid + 128] + bb[tid + 128];
    float o2 = (v2 - mu) * inv * g[tid + 256] + bb[tid + 256];
    float os[3] = {o0, o1, o2};
    #pragma unroll
    for (int j = 0; j < 3; j++) {
        __nv_bfloat16 h = __float2bfloat16(os[j]);
        oh[obase + tid + j*128] = h;
        ol[obase + tid + j*128] = __float2bfloat16(os[j] - __bfloat162float(h));
    }
}

// LN2 (token-major fp32 in) -> split bf16
__global__ void __launch_bounds__(128) ln2_kernel(
    const float* __restrict__ xh, const float* __restrict__ g,
    const float* __restrict__ bb,
    __nv_bfloat16* __restrict__ oh, __nv_bfloat16* __restrict__ ol) {
    __shared__ float sm[8];
    int tok = blockIdx.x;
    int tid = threadIdx.x;
    const float* row = xh + (size_t)tok * Cc;
    size_t obase = (size_t)tok * Cc;
    float v0 = row[tid], v1 = row[tid + 128], v2 = row[tid + 256];
    float s = v0 + v1 + v2;
    float q = v0*v0 + v1*v1 + v2*v2;
    ln_block_reduce(s, q, sm);
    float mu = s * (1.f / Cc);
    float var = q * (1.f / Cc) - mu * mu;
    float inv = rsqrtf(var + 1e-5f);
    float os[3];
    os[0] = (v0 - mu) * inv * g[tid]       + bb[tid];
    os[1] = (v1 - mu) * inv * g[tid + 128] + bb[tid + 128];
    os[2] = (v2 - mu) * inv * g[tid + 256] + bb[tid + 256];
    #pragma unroll
    for (int j = 0; j < 3; j++) {
        __nv_bfloat16 h = __float2bfloat16(os[j]);
        oh[obase + tid + j*128] = h;
        ol[obase + tid + j*128] = __float2bfloat16(os[j] - __bfloat162float(h));
    }
}

// ============================================================================
// Split-bf16 tensor-core GEMM: C[M,N] = epi(A[M,K] @ W[N,K]^T)
// A,W pre-split into (hi,lo) bf16. 3-term MMA: Ah*Wh + Al*Wh + Ah*Wl.
// BM=128 BN=64 BK=32, 256 threads (4x2 warps, warp tile 32x32).
// cp.async 3-stage pipeline, pad-40 rows for conflict-free ldmatrix.
// EPI: 0 = fp32 out, 1 = fp32 + resid, 2 = SiLU + split-bf16 out
// ============================================================================
#define PAD 40
#define A_ELE (128*PAD)
#define W_ELE (64*PAD)
#define STG_ELE (2*A_ELE + 2*W_ELE)
#define GEMM_SMEM_B (3 * STG_ELE * 2)

__device__ __forceinline__ void ldm_x4(uint32_t* r, uint32_t addr) {
    asm volatile("ldmatrix.sync.aligned.m8n8.x4.shared.b16 {%0,%1,%2,%3}, [%4];"
        : "=r"(r[0]), "=r"(r[1]), "=r"(r[2]), "=r"(r[3]) : "r"(addr));
}
__device__ __forceinline__ void mma_bf16(float* c, const uint32_t* a, const uint32_t* b) {
    asm volatile("mma.sync.aligned.m16n8k16.row.col.f32.bf16.bf16.f32 "
        "{%0,%1,%2,%3}, {%4,%5,%6,%7}, {%8,%9}, {%0,%1,%2,%3};"
        : "+f"(c[0]), "+f"(c[1]), "+f"(c[2]), "+f"(c[3])
        : "r"(a[0]), "r"(a[1]), "r"(a[2]), "r"(a[3]), "r"(b[0]), "r"(b[1]));
}
#define CP16(dst, src, sz) \
    asm volatile("cp.async.cg.shared.global [%0], [%1], 16, %2;" :: "r"(dst), "l"(src), "r"(sz))
#define CP_COMMIT() asm volatile("cp.async.commit_group;" ::: "memory")
#define CP_WAIT1()  asm volatile("cp.async.wait_group 1;" ::: "memory")

template<int EPI>
__global__ void __launch_bounds__(256, 2) gemm_split_kernel(
    const __nv_bfloat16* __restrict__ Ahp, const __nv_bfloat16* __restrict__ Alp,
    const __nv_bfloat16* __restrict__ Whp, const __nv_bfloat16* __restrict__ Wlp,
    const float* __restrict__ bns, const float* __restrict__ bnt,
    const float* __restrict__ resid, float* __restrict__ Cout,
    __nv_bfloat16* __restrict__ Oh, __nv_bfloat16* __restrict__ Ol,
    int M, int N, int K) {
    extern __shared__ __align__(16) __nv_bfloat16 smem[];
    const int tid = threadIdx.x;
    const int wid = tid >> 5, lane = tid & 31;
    const int m0 = blockIdx.y * 128, n0 = blockIdx.x * 64;
    const int m_off = (wid & 3) * 32, n_off = (wid >> 2) * 32;
    const int nk = K >> 5;

    const int lrow = tid >> 2, lgrp = tid & 3;

    float acc[2][4][4];
    #pragma unroll
    for (int i = 0; i < 2; i++)
        #pragma unroll
        for (int j = 0; j < 4; j++)
            #pragma unroll
            for (int e = 0; e < 4; e++) acc[i][j][e] = 0.f;

    // --- async stage loader ---
    auto issue = [&](int k0, int st) {
        __nv_bfloat16* base = smem + st * STG_ELE;
        #pragma unroll
        for (int it = 0; it < 2; it++) {
            int r = lrow + it * 64;
            int gm = m0 + r;
            int ok = (gm < M);
            size_t srow = (size_t)(ok ? gm : 0) * K + k0 + lgrp * 8;
            CP16(smem_u32(base + r * PAD + lgrp * 8),         Ahp + srow, ok ? 16 : 0);
            CP16(smem_u32(base + A_ELE + r * PAD + lgrp * 8), Alp + srow, ok ? 16 : 0);
        }
        {
            size_t srow = (size_t)(n0 + lrow) * K + k0 + lgrp * 8;
            CP16(smem_u32(base + 2*A_ELE + lrow * PAD + lgrp * 8),         Whp + srow, 16);
            CP16(smem_u32(base + 2*A_ELE + W_ELE + lrow * PAD + lgrp * 8), Wlp + srow, 16);
        }
    };

    issue(0, 0);  CP_COMMIT();
    issue(32, 1); CP_COMMIT();

    const int frow = lane & 15, fsel = (lane >> 4) * 8;

    for (int k = 0; k < nk; k++) {
        CP_WAIT1();
        __syncthreads();
        if (k + 2 < nk) issue((k + 2) * 32, (k + 2) % 3);
        CP_COMMIT();

        const __nv_bfloat16* base = smem + (k % 3) * STG_ELE;
        const __nv_bfloat16* sAh = base;
        const __nv_bfloat16* sAl = base + A_ELE;
        const __nv_bfloat16* sWh = base + 2*A_ELE;
        const __nv_bfloat16* sWl = base + 2*A_ELE + W_ELE;

        #pragma unroll
        for (int ks = 0; ks < 2; ks++) {
            const int kc = ks * 16 + fsel;
            uint32_t ah[2][4], al[2][4], bh[4][2], bl[4][2];
            #pragma unroll
            for (int mt = 0; mt < 2; mt++) {
                ldm_x4(ah[mt], smem_u32(sAh + (m_off + mt*16 + frow) * PAD + kc));
                ldm_x4(al[mt], smem_u32(sAl + (m_off + mt*16 + frow) * PAD + kc));
            }
            #pragma unroll
            for (int np = 0; np < 2; np++) {
                uint32_t r[4];
                ldm_x4(r, smem_u32(sWh + (n_off + np*16 + frow) * PAD + kc));
                bh[2*np][0] = r[0]; bh[2*np][1] = r[2];
                bh[2*np+1][0] = r[1]; bh[2*np+1][1] = r[3];
                ldm_x4(r, smem_u32(sWl + (n_off + np*16 + frow) * PAD + kc));
                bl[2*np][0] = r[0]; bl[2*np][1] = r[2];
                bl[2*np+1][0] = r[1]; bl[2*np+1][1] = r[3];
            }
            #pragma unroll
            for (int mt = 0; mt < 2; mt++)
                #pragma unroll
                for (int nt = 0; nt < 4; nt++) {
                    mma_bf16(acc[mt][nt], ah[mt], bh[nt]);
                    mma_bf16(acc[mt][nt], al[mt], bh[nt]);
                    mma_bf16(acc[mt][nt], ah[mt], bl[nt]);
                }
        }
        __syncthreads();
    }

    // epilogue
    const int erow = lane >> 2, ecol = (lane & 3) * 2;
    #pragma unroll
    for (int mt = 0; mt < 2; mt++) {
        #pragma unroll
        for (int half = 0; half < 2; half++) {
            int m = m0 + m_off + mt * 16 + erow + half * 8;
            if (m < M) {
                size_t rowoff = (size_t)m * N;
                #pragma unroll
                for (int nt = 0; nt < 4; nt++) {
                    int n = n0 + n_off + nt * 8 + ecol;
                    float v0 = acc[mt][nt][half*2]     * bns[n]     + bnt[n];
                    float v1 = acc[mt][nt][half*2 + 1] * bns[n + 1] + bnt[n + 1];
                    if (EPI == 2) {
                        v0 = v0 / (1.f + __expf(-v0));
                        v1 = v1 / (1.f + __expf(-v1));
                        split_store(v0, v1, Oh + rowoff + n, Ol + rowoff + n);
                    } else {
                        if (EPI == 1) {
                            float2 rr = *(const float2*)(resid + rowoff + n);
                            v0 += rr.x; v1 += rr.y;
                        }
                        *(float2*)(Cout + rowoff + n) = make_float2(v0, v1);
                    }
                }
            }
        }
    }
}

// ---------------- attention: one block per (window, head) ----------------
__global__ void __launch_bounds__(256) attn_kernel(
    const float* __restrict__ qkv,
    __nv_bfloat16* __restrict__ oth, __nv_bfloat16* __restrict__ otl) {
    __shared__ float qs[64][49];
    __shared__ float ks[64][49];
    __shared__ float S[64][65];
    const int blk = blockIdx.x;
    const int win = blk >> 3, h = blk & 7;
    const int tid = threadIdx.x;
    const float scale = 0.144337567297406f;
    const size_t base = (size_t)win * 64 * 1152 + h * 48;

    for (int idx = tid; idx < 64 * 48; idx += 256) {
        int l = idx / 48, d = idx - l * 48;
        qs[l][d] = qkv[base + (size_t)l * 1152 + d] * scale;
        ks[l][d] = qkv[base + (size_t)l * 1152 + 384 + d];
    }
    __syncthreads();

    const int tx = tid & 15, ty = tid >> 4;
    float acc[4][4];
    #pragma unroll
    for (int i = 0; i < 4; i++)
        #pragma unroll
        for (int j = 0; j < 4; j++) acc[i][j] = 0.f;
    #pragma unroll 8
    for (int d = 0; d < 48; d++) {
        float a[4], bv[4];
        #pragma unroll
        for (int i = 0; i < 4; i++) a[i] = qs[ty * 4 + i][d];
        #pragma unroll
        for (int j = 0; j < 4; j++) bv[j] = ks[tx * 4 + j][d];
        #pragma unroll
        for (int i = 0; i < 4; i++)
            #pragma unroll
            for (int j = 0; j < 4; j++)
                acc[i][j] += a[i] * bv[j];
    }
    #pragma unroll
    for (int i = 0; i < 4; i++)
        #pragma unroll
        for (int j = 0; j < 4; j++)
            S[ty * 4 + i][tx * 4 + j] = acc[i][j];
    __syncthreads();

    for (int idx = tid; idx < 64 * 48; idx += 256) {
        int l = idx / 48, d = idx - l * 48;
        qs[l][d] = qkv[base + (size_t)l * 1152 + 768 + d];
    }
    const int wrp = tid >> 5, lane = tid & 31;
    #pragma unroll
    for (int rr = 0; rr < 8; rr++) {
        int rw = wrp * 8 + rr;
        float e0 = S[rw][lane], e1 = S[rw][lane + 32];
        float mx = fmaxf(e0, e1);
        #pragma unroll
        for (int o = 16; o; o >>= 1) mx = fmaxf(mx, __shfl_xor_sync(0xffffffffu, mx, o));
        e0 = __expf(e0 - mx); e1 = __expf(e1 - mx);
        float sum = e0 + e1;
        #pragma unroll
        for (int o = 16; o; o >>= 1) sum += __shfl_xor_sync(0xffffffffu, sum, o);
        float inv = 1.f / sum;
        S[rw][lane] = e0 * inv;
        S[rw][lane + 32] = e1 * inv;
    }
    __syncthreads();

    float o[4][3];
    #pragma unroll
    for (int i = 0; i < 4; i++)
        #pragma unroll
        for (int c = 0; c < 3; c++) o[i][c] = 0.f;
    #pragma unroll 4
    for (int j = 0; j < 64; j++) {
        float p[4], vv[3];
        #pragma unroll
        for (int i = 0; i < 4; i++) p[i] = S[ty * 4 + i][j];
        #pragma unroll
        for (int c = 0; c < 3; c++) vv[c] = qs[j][tx * 3 + c];
        #pragma unroll
        for (int i = 0; i < 4; i++)
            #pragma unroll
            for (int c = 0; c < 3; c++)
                o[i][c] += p[i] * vv[c];
    }

    const int b  = win / (nHw * nWw);
    const int r2 = win % (nHw * nWw);
    const int hwi = r2 / nWw, wwi = r2 % nWw;
    #pragma unroll
    for (int i = 0; i < 4; i++) {
        int l = ty * 4 + i;
        int hp = hwi * 4 + (l >> 4), wp = wwi * 16 + (l & 15);
        if (hp < Hc && wp < Wc) {
            size_t row = ((size_t)(b * Hc + hp) * Wc + wp) * Cc + h * 48 + tx * 3;
            #pragma unroll
            for (int c = 0; c < 3; c++) {
                float v = o[i][c];
                __nv_bfloat16 hb = __float2bfloat16(v);
                oth[row + c] = hb;
                otl[row + c] = __float2bfloat16(v - __bfloat162float(hb));
            }
        }
    }
}

// ---------------- host ----------------
extern "C" void kernel_launch(void* const* d_in, const int* in_sizes, int n_in,
                              void* d_out, int out_size) {
    const float* x       = (const float*)d_in[0];
    const float* qkv_w   = (const float*)d_in[1];
    const float* qkv_bn  = (const float*)d_in[2];
    const float* proj_w  = (const float*)d_in[3];
    const float* proj_bn = (const float*)d_in[4];
    const float* n1_g    = (const float*)d_in[5];
    const float* n1_b    = (const float*)d_in[6];
    const float* n2_g    = (const float*)d_in[7];
    const float* n2_b    = (const float*)d_in[8];
    const float* mlp1_w  = (const float*)d_in[9];
    const float* mlp1_bn = (const float*)d_in[10];
    const float* mlp2_w  = (const float*)d_in[11];
    const float* mlp2_bn = (const float*)d_in[12];
    float* out = (float*)d_out;

    float *xh, *qkv, *bns, *bnt;
    __nv_bfloat16 *acth, *actl, *oth, *otl, *hh, *hl;
    __nv_bfloat16 *wqh, *wql, *wph, *wpl, *w1h, *w1l, *w2h, *w2l;
    cudaGetSymbolAddress((void**)&xh,   g_xh);
    cudaGetSymbolAddress((void**)&qkv,  g_qkv);
    cudaGetSymbolAddress((void**)&bns,  g_bns);
    cudaGetSymbolAddress((void**)&bnt,  g_bnt);
    cudaGetSymbolAddress((void**)&acth, g_act_h);
    cudaGetSymbolAddress((void**)&actl, g_act_l);
    cudaGetSymbolAddress((void**)&oth,  g_ot_h);
    cudaGetSymbolAddress((void**)&otl,  g_ot_l);
    cudaGetSymbolAddress((void**)&hh,   g_h_h);
    cudaGetSymbolAddress((void**)&hl,   g_h_l);
    cudaGetSymbolAddress((void**)&wqh,  g_wq_h);
    cudaGetSymbolAddress((void**)&wql,  g_wq_l);
    cudaGetSymbolAddress((void**)&wph,  g_wp_h);
    cudaGetSymbolAddress((void**)&wpl,  g_wp_l);
    cudaGetSymbolAddress((void**)&w1h,  g_w1_h);
    cudaGetSymbolAddress((void**)&w1l,  g_w1_l);
    cudaGetSymbolAddress((void**)&w2h,  g_w2_h);
    cudaGetSymbolAddress((void**)&w2l,  g_w2_l);

    cudaFuncSetAttribute(gemm_split_kernel<0>, cudaFuncAttributeMaxDynamicSharedMemorySize, GEMM_SMEM_B);
    cudaFuncSetAttribute(gemm_split_kernel<1>, cudaFuncAttributeMaxDynamicSharedMemorySize, GEMM_SMEM_B);
    cudaFuncSetAttribute(gemm_split_kernel<2>, cudaFuncAttributeMaxDynamicSharedMemorySize, GEMM_SMEM_B);

    bn_prep_kernel<<<5, 256>>>(qkv_bn, 1152, bns + 0,    bnt + 0);
    bn_prep_kernel<<<2, 256>>>(proj_bn, 384, bns + 1152, bnt + 1152);
    bn_prep_kernel<<<3, 256>>>(mlp1_bn, 768, bns + 1536, bnt + 1536);
    bn_prep_kernel<<<2, 256>>>(mlp2_bn, 384, bns + 2304, bnt + 2304);

    wsplit_kernel<<<(442368/2 + 255)/256, 256>>>(qkv_w,  442368, wqh, wql);
    wsplit_kernel<<<(147456/2 + 255)/256, 256>>>(proj_w, 147456, wph, wpl);
    wsplit_kernel<<<(294912/2 + 255)/256, 256>>>(mlp1_w, 294912, w1h, w1l);
    wsplit_kernel<<<(294912/2 + 255)/256, 256>>>(mlp2_w, 294912, w2h, w2l);

    transpose_in_kernel<<<dim3(811, 12, Bc), dim3(32, 8)>>>(x, xh);
    ln1_window_kernel<<<NTOKP, 128>>>(xh, n1_g, n1_b, acth, actl);

    // qkv = BN(win @ qkv_w^T)   M=115456, N=1152, K=384
    gemm_split_kernel<0><<<dim3(18, 902), 256, GEMM_SMEM_B>>>(
        acth, actl, wqh, wql, bns, bnt, nullptr, qkv, nullptr, nullptr,
        NTOKP, 1152, Cc);

    attn_kernel<<<NWIN * NHh, 256>>>(qkv, oth, otl);

    // xh += BN(otok @ proj_w^T)  M=103684, N=384, K=384
    gemm_split_kernel<1><<<dim3(6, 811), 256, GEMM_SMEM_B>>>(
        oth, otl, wph, wpl, bns + 1152, bnt + 1152, xh, xh, nullptr, nullptr,
        NTOK, Cc, Cc);

    ln2_kernel<<<NTOK, 128>>>(xh, n2_g, n2_b, acth, actl);

    // h = silu(BN(xn2 @ mlp1_w^T))  M=103684, N=768, K=384 -> split bf16
    gemm_split_kernel<2><<<dim3(12, 811), 256, GEMM_SMEM_B>>>(
        acth, actl, w1h, w1l, bns + 1536, bnt + 1536, nullptr, nullptr, hh, hl,
        NTOK, 2 * Cc, Cc);

    // xh += BN(h @ mlp2_w^T)  M=103684, N=384, K=768
    gemm_split_kernel<1><<<dim3(6, 811), 256, GEMM_SMEM_B>>>(
        hh, hl, w2h, w2l, bns + 2304, bnt + 2304, xh, xh, nullptr, nullptr,
        NTOK, Cc, 2 * Cc);

    transpose_out_kernel<<<dim3(811, 12, Bc), dim3(32, 8)>>>(xh, out);
}

// round 6
// speedup vs baseline: 3.6077x; 1.6978x over previous
#include <cuda_runtime.h>
#include <cuda_fp16.h>
#include <math.h>
#include <stdint.h>

// ---------------- problem constants ----------------
#define Bc 4
#define Cc 384
#define Hc 161
#define Wc 161
#define HWc (Hc*Wc)            // 25921
#define NTOK (Bc*HWc)          // 103684
#define nHw 41
#define nWw 11
#define NWIN (Bc*nHw*nWw)      // 1804
#define NHh 8
#define NTOKP (NWIN*64)        // 115456

// ---------------- scratch (static device, no allocs) ----------------
__device__ float g_xh[(size_t)NTOK*Cc];
__device__ __half g_qkv[(size_t)NTOKP*1152];
__device__ __half g_act[(size_t)NTOKP*Cc];     // LN1 windowed / LN2 out
__device__ __half g_ot[(size_t)NTOK*Cc];       // attention out
__device__ __half g_h[(size_t)NTOK*2*Cc];      // mlp hidden
__device__ __half g_wq[1152*384];
__device__ __half g_wp[384*384];
__device__ __half g_w1[768*384];
__device__ __half g_w2[384*768];
__device__ float g_bns[2688];
__device__ float g_bnt[2688];

__device__ __forceinline__ uint32_t smem_u32(const void* p) {
    uint32_t a;
    asm("{ .reg .u64 t; cvta.to.shared.u64 t, %1; cvt.u32.u64 %0, t; }" : "=r"(a) : "l"(p));
    return a;
}

// ---------------- BN prep ----------------
__global__ void bn_prep_kernel(const float* __restrict__ p, int n,
                               float* __restrict__ s, float* __restrict__ t) {
    int i = blockIdx.x * blockDim.x + threadIdx.x;
    if (i < n) {
        float g = p[i], b = p[n + i], rm = p[2*n + i], rv = p[3*n + i];
        float sc = g * rsqrtf(rv + 1e-3f);
        s[i] = sc;
        t[i] = b - rm * sc;
    }
}

// ---------------- weight convert fp32 -> fp16 ----------------
__global__ void wconv_kernel(const float* __restrict__ w, int n, __half* __restrict__ wh) {
    int i = blockIdx.x * blockDim.x + threadIdx.x;
    if (i < n) wh[i] = __float2half_rn(w[i]);
}

// ---------------- transposes ----------------
__global__ void transpose_in_kernel(const float* __restrict__ x, float* __restrict__ xh) {
    __shared__ float tile[32][33];
    int b = blockIdx.z, c0 = blockIdx.y * 32, s0 = blockIdx.x * 32;
    int tx = threadIdx.x, ty = threadIdx.y;
    #pragma unroll
    for (int r = 0; r < 32; r += 8) {
        int c = c0 + ty + r, s = s0 + tx;
        if (s < HWc) tile[ty + r][tx] = x[((size_t)b * Cc + c) * HWc + s];
    }
    __syncthreads();
    #pragma unroll
    for (int r = 0; r < 32; r += 8) {
        int c = c0 + tx, s = s0 + ty + r;
        if (s < HWc) xh[((size_t)b * HWc + s) * Cc + c] = tile[tx][ty + r];
    }
}
__global__ void transpose_out_kernel(const float* __restrict__ xh, float* __restrict__ out) {
    __shared__ float tile[32][33];
    int b = blockIdx.z, c0 = blockIdx.y * 32, s0 = blockIdx.x * 32;
    int tx = threadIdx.x, ty = threadIdx.y;
    #pragma unroll
    for (int r = 0; r < 32; r += 8) {
        int s = s0 + ty + r, c = c0 + tx;
        if (s < HWc) tile[ty + r][tx] = xh[((size_t)b * HWc + s) * Cc + c];
    }
    __syncthreads();
    #pragma unroll
    for (int r = 0; r < 32; r += 8) {
        int s = s0 + tx, c = c0 + ty + r;
        if (s < HWc) out[((size_t)b * Cc + c) * HWc + s] = tile[tx][ty + r];
    }
}

// ---------------- LN reduce ----------------
__device__ __forceinline__ void ln_block_reduce(float& s, float& q, float* sm) {
    #pragma unroll
    for (int o = 16; o; o >>= 1) {
        s += __shfl_down_sync(0xffffffffu, s, o);
        q += __shfl_down_sync(0xffffffffu, q, o);
    }
    int w = threadIdx.x >> 5, lane = threadIdx.x & 31;
    if (!lane) { sm[w] = s; sm[4 + w] = q; }
    __syncthreads();
    s = sm[0] + sm[1] + sm[2] + sm[3];
    q = sm[4] + sm[5] + sm[6] + sm[7];
}

// LN1 + window partition -> fp16
__global__ void __launch_bounds__(128) ln1_window_kernel(
    const float* __restrict__ xh, const float* __restrict__ g,
    const float* __restrict__ bb, __half* __restrict__ oh) {
    __shared__ float sm[8];
    int gidx = blockIdx.x;
    int wi = gidx >> 6, l = gidx & 63;
    int b  = wi / (nHw * nWw);
    int r  = wi % (nHw * nWw);
    int hwi = r / nWw, wwi = r % nWw;
    int hp = hwi * 4 + (l >> 4), wp = wwi * 16 + (l & 15);
    size_t obase = (size_t)gidx * Cc;
    int tid = threadIdx.x;
    if (hp >= Hc || wp >= Wc) {
        __half z = __float2half(0.f);
        oh[obase + tid] = z; oh[obase + tid + 128] = z; oh[obase + tid + 256] = z;
        return;
    }
    const float* row = xh + ((size_t)(b * Hc + hp) * Wc + wp) * Cc;
    float v0 = row[tid], v1 = row[tid + 128], v2 = row[tid + 256];
    float s = v0 + v1 + v2;
    float q = v0*v0 + v1*v1 + v2*v2;
    ln_block_reduce(s, q, sm);
    float mu = s * (1.f / Cc);
    float var = q * (1.f / Cc) - mu * mu;
    float inv = rsqrtf(var + 1e-5f);
    oh[obase + tid]       = __float2half_rn((v0 - mu) * inv * g[tid]       + bb[tid]);
    oh[obase + tid + 128] = __float2half_rn((v1 - mu) * inv * g[tid + 128] + bb[tid + 128]);
    oh[obase + tid + 256] = __float2half_rn((v2 - mu) * inv * g[tid + 256] + bb[tid + 256]);
}

// LN2 (token-major fp32 in) -> fp16
__global__ void __launch_bounds__(128) ln2_kernel(
    const float* __restrict__ xh, const float* __restrict__ g,
    const float* __restrict__ bb, __half* __restrict__ oh) {
    __shared__ float sm[8];
    int tok = blockIdx.x;
    int tid = threadIdx.x;
    const float* row = xh + (size_t)tok * Cc;
    size_t obase = (size_t)tok * Cc;
    float v0 = row[tid], v1 = row[tid + 128], v2 = row[tid + 256];
    float s = v0 + v1 + v2;
    float q = v0*v0 + v1*v1 + v2*v2;
    ln_block_reduce(s, q, sm);
    float mu = s * (1.f / Cc);
    float var = q * (1.f / Cc) - mu * mu;
    float inv = rsqrtf(var + 1e-5f);
    oh[obase + tid]       = __float2half_rn((v0 - mu) * inv * g[tid]       + bb[tid]);
    oh[obase + tid + 128] = __float2half_rn((v1 - mu) * inv * g[tid + 128] + bb[tid + 128]);
    oh[obase + tid + 256] = __float2half_rn((v2 - mu) * inv * g[tid + 256] + bb[tid + 256]);
}

// ============================================================================
// fp16 tensor-core GEMM: C[M,N] = epi(A[M,K] @ W[N,K]^T), fp32 accumulate.
// BM=128 BN=64 BK=32, 256 threads (4x2 warps, warp tile 32x32).
// cp.async 3-stage pipeline, pad-40 rows for conflict-free ldmatrix.
// EPI: 0 = BN -> fp16 out, 1 = BN + resid -> fp32 out, 2 = BN+SiLU -> fp16 out
// ============================================================================
#define PAD 40
#define A_ELE (128*PAD)
#define W_ELE (64*PAD)
#define STG_ELE (A_ELE + W_ELE)
#define GEMM_SMEM_B (3 * STG_ELE * 2)

__device__ __forceinline__ void ldm_x4(uint32_t* r, uint32_t addr) {
    asm volatile("ldmatrix.sync.aligned.m8n8.x4.shared.b16 {%0,%1,%2,%3}, [%4];"
        : "=r"(r[0]), "=r"(r[1]), "=r"(r[2]), "=r"(r[3]) : "r"(addr));
}
__device__ __forceinline__ void mma_f16(float* c, const uint32_t* a, const uint32_t* b) {
    asm volatile("mma.sync.aligned.m16n8k16.row.col.f32.f16.f16.f32 "
        "{%0,%1,%2,%3}, {%4,%5,%6,%7}, {%8,%9}, {%0,%1,%2,%3};"
        : "+f"(c[0]), "+f"(c[1]), "+f"(c[2]), "+f"(c[3])
        : "r"(a[0]), "r"(a[1]), "r"(a[2]), "r"(a[3]), "r"(b[0]), "r"(b[1]));
}
#define CP16(dst, src, sz) \
    asm volatile("cp.async.cg.shared.global [%0], [%1], 16, %2;" :: "r"(dst), "l"(src), "r"(sz))
#define CP_COMMIT() asm volatile("cp.async.commit_group;" ::: "memory")
#define CP_WAIT1()  asm volatile("cp.async.wait_group 1;" ::: "memory")

template<int EPI>
__global__ void __launch_bounds__(256, 2) gemm_f16_kernel(
    const __half* __restrict__ A, const __half* __restrict__ W,
    const float* __restrict__ bns, const float* __restrict__ bnt,
    const float* __restrict__ resid, float* __restrict__ Cf,
    __half* __restrict__ Ch,
    int M, int N, int K) {
    extern __shared__ __align__(16) __half smem[];
    const int tid = threadIdx.x;
    const int wid = tid >> 5, lane = tid & 31;
    const int m0 = blockIdx.y * 128, n0 = blockIdx.x * 64;
    const int m_off = (wid & 3) * 32, n_off = (wid >> 2) * 32;
    const int nk = K >> 5;

    const int lrow = tid >> 2, lgrp = (tid & 3) * 8;

    float acc[2][4][4];
    #pragma unroll
    for (int i = 0; i < 2; i++)
        #pragma unroll
        for (int j = 0; j < 4; j++)
            #pragma unroll
            for (int e = 0; e < 4; e++) acc[i][j][e] = 0.f;

    auto issue = [&](int k0, int st) {
        __half* base = smem + st * STG_ELE;
        #pragma unroll
        for (int it = 0; it < 2; it++) {
            int r = lrow + it * 64;
            int gm = m0 + r;
            int ok = (gm < M);
            const __half* src = A + (size_t)(ok ? gm : 0) * K + k0 + lgrp;
            CP16(smem_u32(base + r * PAD + lgrp), src, ok ? 16 : 0);
        }
        {
            const __half* src = W + (size_t)(n0 + lrow) * K + k0 + lgrp;
            CP16(smem_u32(base + A_ELE + lrow * PAD + lgrp), src, 16);
        }
    };

    issue(0, 0);  CP_COMMIT();
    issue(32, 1); CP_COMMIT();

    const int frow = lane & 15, fsel = (lane >> 4) * 8;

    for (int k = 0; k < nk; k++) {
        CP_WAIT1();
        __syncthreads();
        if (k + 2 < nk) issue((k + 2) * 32, (k + 2) % 3);
        CP_COMMIT();

        const __half* sA = smem + (k % 3) * STG_ELE;
        const __half* sW = sA + A_ELE;

        #pragma unroll
        for (int ks = 0; ks < 2; ks++) {
            const int kc = ks * 16 + fsel;
            uint32_t af[2][4], bf[4][2];
            #pragma unroll
            for (int mt = 0; mt < 2; mt++)
                ldm_x4(af[mt], smem_u32(sA + (m_off + mt*16 + frow) * PAD + kc));
            #pragma unroll
            for (int np = 0; np < 2; np++) {
                uint32_t r[4];
                ldm_x4(r, smem_u32(sW + (n_off + np*16 + frow) * PAD + kc));
                bf[2*np][0] = r[0]; bf[2*np][1] = r[2];
                bf[2*np+1][0] = r[1]; bf[2*np+1][1] = r[3];
            }
            #pragma unroll
            for (int mt = 0; mt < 2; mt++)
                #pragma unroll
                for (int nt = 0; nt < 4; nt++)
                    mma_f16(acc[mt][nt], af[mt], bf[nt]);
        }
        __syncthreads();
    }

    // epilogue
    const int erow = lane >> 2, ecol = (lane & 3) * 2;
    #pragma unroll
    for (int mt = 0; mt < 2; mt++) {
        #pragma unroll
        for (int half = 0; half < 2; half++) {
            int m = m0 + m_off + mt * 16 + erow + half * 8;
            if (m < M) {
                size_t rowoff = (size_t)m * N;
                #pragma unroll
                for (int nt = 0; nt < 4; nt++) {
                    int n = n0 + n_off + nt * 8 + ecol;
                    float v0 = acc[mt][nt][half*2]     * bns[n]     + bnt[n];
                    float v1 = acc[mt][nt][half*2 + 1] * bns[n + 1] + bnt[n + 1];
                    if (EPI == 2) {
                        v0 = v0 / (1.f + __expf(-v0));
                        v1 = v1 / (1.f + __expf(-v1));
                    }
                    if (EPI == 1) {
                        float2 rr = *(const float2*)(resid + rowoff + n);
                        v0 += rr.x; v1 += rr.y;
                        *(float2*)(Cf + rowoff + n) = make_float2(v0, v1);
                    } else {
                        __half2 hv = __floats2half2_rn(v0, v1);
                        *(__half2*)(Ch + rowoff + n) = hv;
                    }
                }
            }
        }
    }
}

// ---------------- attention: one block per (window, head) ----------------
__global__ void __launch_bounds__(256) attn_kernel(
    const __half* __restrict__ qkv, __half* __restrict__ oth) {
    __shared__ float qs[64][49];
    __shared__ float ks[64][49];
    __shared__ float S[64][65];
    const int blk = blockIdx.x;
    const int win = blk >> 3, h = blk & 7;
    const int tid = threadIdx.x;
    const float scale = 0.144337567297406f;
    const size_t base = (size_t)win * 64 * 1152 + h * 48;

    for (int idx = tid; idx < 64 * 48; idx += 256) {
        int l = idx / 48, d = idx - l * 48;
        qs[l][d] = __half2float(qkv[base + (size_t)l * 1152 + d]) * scale;
        ks[l][d] = __half2float(qkv[base + (size_t)l * 1152 + 384 + d]);
    }
    __syncthreads();

    const int tx = tid & 15, ty = tid >> 4;
    float acc[4][4];
    #pragma unroll
    for (int i = 0; i < 4; i++)
        #pragma unroll
        for (int j = 0; j < 4; j++) acc[i][j] = 0.f;
    #pragma unroll 8
    for (int d = 0; d < 48; d++) {
        float a[4], bv[4];
        #pragma unroll
        for (int i = 0; i < 4; i++) a[i] = qs[ty * 4 + i][d];
        #pragma unroll
        for (int j = 0; j < 4; j++) bv[j] = ks[tx * 4 + j][d];
        #pragma unroll
        for (int i = 0; i < 4; i++)
            #pragma unroll
            for (int j = 0; j < 4; j++)
                acc[i][j] += a[i] * bv[j];
    }
    #pragma unroll
    for (int i = 0; i < 4; i++)
        #pragma unroll
        for (int j = 0; j < 4; j++)
            S[ty * 4 + i][tx * 4 + j] = acc[i][j];
    __syncthreads();

    for (int idx = tid; idx < 64 * 48; idx += 256) {
        int l = idx / 48, d = idx - l * 48;
        qs[l][d] = __half2float(qkv[base + (size_t)l * 1152 + 768 + d]);
    }
    const int wrp = tid >> 5, lane = tid & 31;
    #pragma unroll
    for (int rr = 0; rr < 8; rr++) {
        int rw = wrp * 8 + rr;
        float e0 = S[rw][lane], e1 = S[rw][lane + 32];
        float mx = fmaxf(e0, e1);
        #pragma unroll
        for (int o = 16; o; o >>= 1) mx = fmaxf(mx, __shfl_xor_sync(0xffffffffu, mx, o));
        e0 = __expf(e0 - mx); e1 = __expf(e1 - mx);
        float sum = e0 + e1;
        #pragma unroll
        for (int o = 16; o; o >>= 1) sum += __shfl_xor_sync(0xffffffffu, sum, o);
        float inv = 1.f / sum;
        S[rw][lane] = e0 * inv;
        S[rw][lane + 32] = e1 * inv;
    }
    __syncthreads();

    float o[4][3];
    #pragma unroll
    for (int i = 0; i < 4; i++)
        #pragma unroll
        for (int c = 0; c < 3; c++) o[i][c] = 0.f;
    #pragma unroll 4
    for (int j = 0; j < 64; j++) {
        float p[4], vv[3];
        #pragma unroll
        for (int i = 0; i < 4; i++) p[i] = S[ty * 4 + i][j];
        #pragma unroll
        for (int c = 0; c < 3; c++) vv[c] = qs[j][tx * 3 + c];
        #pragma unroll
        for (int i = 0; i < 4; i++)
            #pragma unroll
            for (int c = 0; c < 3; c++)
                o[i][c] += p[i] * vv[c];
    }

    const int b  = win / (nHw * nWw);
    const int r2 = win % (nHw * nWw);
    const int hwi = r2 / nWw, wwi = r2 % nWw;
    #pragma unroll
    for (int i = 0; i < 4; i++) {
        int l = ty * 4 + i;
        int hp = hwi * 4 + (l >> 4), wp = wwi * 16 + (l & 15);
        if (hp < Hc && wp < Wc) {
            size_t row = ((size_t)(b * Hc + hp) * Wc + wp) * Cc + h * 48 + tx * 3;
            oth[row + 0] = __float2half_rn(o[i][0]);
            oth[row + 1] = __float2half_rn(o[i][1]);
            oth[row + 2] = __float2half_rn(o[i][2]);
        }
    }
}

// ---------------- host ----------------
extern "C" void kernel_launch(void* const* d_in, const int* in_sizes, int n_in,
                              void* d_out, int out_size) {
    const float* x       = (const float*)d_in[0];
    const float* qkv_w   = (const float*)d_in[1];
    const float* qkv_bn  = (const float*)d_in[2];
    const float* proj_w  = (const float*)d_in[3];
    const float* proj_bn = (const float*)d_in[4];
    const float* n1_g    = (const float*)d_in[5];
    const float* n1_b    = (const float*)d_in[6];
    const float* n2_g    = (const float*)d_in[7];
    const float* n2_b    = (const float*)d_in[8];
    const float* mlp1_w  = (const float*)d_in[9];
    const float* mlp1_bn = (const float*)d_in[10];
    const float* mlp2_w  = (const float*)d_in[11];
    const float* mlp2_bn = (const float*)d_in[12];
    float* out = (float*)d_out;

    float *xh, *bns, *bnt;
    __half *qkv, *act, *ot, *hbuf, *wq, *wp, *w1, *w2;
    cudaGetSymbolAddress((void**)&xh,   g_xh);
    cudaGetSymbolAddress((void**)&qkv,  g_qkv);
    cudaGetSymbolAddress((void**)&bns,  g_bns);
    cudaGetSymbolAddress((void**)&bnt,  g_bnt);
    cudaGetSymbolAddress((void**)&act,  g_act);
    cudaGetSymbolAddress((void**)&ot,   g_ot);
    cudaGetSymbolAddress((void**)&hbuf, g_h);
    cudaGetSymbolAddress((void**)&wq,   g_wq);
    cudaGetSymbolAddress((void**)&wp,   g_wp);
    cudaGetSymbolAddress((void**)&w1,   g_w1);
    cudaGetSymbolAddress((void**)&w2,   g_w2);

    cudaFuncSetAttribute(gemm_f16_kernel<0>, cudaFuncAttributeMaxDynamicSharedMemorySize, GEMM_SMEM_B);
    cudaFuncSetAttribute(gemm_f16_kernel<1>, cudaFuncAttributeMaxDynamicSharedMemorySize, GEMM_SMEM_B);
    cudaFuncSetAttribute(gemm_f16_kernel<2>, cudaFuncAttributeMaxDynamicSharedMemorySize, GEMM_SMEM_B);

    bn_prep_kernel<<<5, 256>>>(qkv_bn, 1152, bns + 0,    bnt + 0);
    bn_prep_kernel<<<2, 256>>>(proj_bn, 384, bns + 1152, bnt + 1152);
    bn_prep_kernel<<<3, 256>>>(mlp1_bn, 768, bns + 1536, bnt + 1536);
    bn_prep_kernel<<<2, 256>>>(mlp2_bn, 384, bns + 2304, bnt + 2304);

    wconv_kernel<<<(442368 + 255)/256, 256>>>(qkv_w,  442368, wq);
    wconv_kernel<<<(147456 + 255)/256, 256>>>(proj_w, 147456, wp);
    wconv_kernel<<<(294912 + 255)/256, 256>>>(mlp1_w, 294912, w1);
    wconv_kernel<<<(294912 + 255)/256, 256>>>(mlp2_w, 294912, w2);

    transpose_in_kernel<<<dim3(811, 12, Bc), dim3(32, 8)>>>(x, xh);
    ln1_window_kernel<<<NTOKP, 128>>>(xh, n1_g, n1_b, act);

    // qkv = BN(win @ qkv_w^T) -> fp16   M=115456, N=1152, K=384
    gemm_f16_kernel<0><<<dim3(18, 902), 256, GEMM_SMEM_B>>>(
        act, wq, bns, bnt, nullptr, nullptr, qkv, NTOKP, 1152, Cc);

    attn_kernel<<<NWIN * NHh, 256>>>(qkv, ot);

    // xh += BN(otok @ proj_w^T)  M=103684, N=384, K=384
    gemm_f16_kernel<1><<<dim3(6, 811), 256, GEMM_SMEM_B>>>(
        ot, wp, bns + 1152, bnt + 1152, xh, xh, nullptr, NTOK, Cc, Cc);

    ln2_kernel<<<NTOK, 128>>>(xh, n2_g, n2_b, act);

    // h = silu(BN(xn2 @ mlp1_w^T)) -> fp16  M=103684, N=768, K=384
    gemm_f16_kernel<2><<<dim3(12, 811), 256, GEMM_SMEM_B>>>(
        act, w1, bns + 1536, bnt + 1536, nullptr, nullptr, hbuf, NTOK, 2 * Cc, Cc);

    // xh += BN(h @ mlp2_w^T)  M=103684, N=384, K=768
    gemm_f16_kernel<1><<<dim3(6, 811), 256, GEMM_SMEM_B>>>(
        hbuf, w2, bns + 2304, bnt + 2304, xh, xh, nullptr, NTOK, Cc, 2 * Cc);

    transpose_out_kernel<<<dim3(811, 12, Bc), dim3(32, 8)>>>(xh, out);
}

// round 7
// speedup vs baseline: 4.4526x; 1.2342x over previous
#include <cuda_runtime.h>
#include <cuda_fp16.h>
#include <math.h>
#include <stdint.h>

// ---------------- problem constants ----------------
#define Bc 4
#define Cc 384
#define Hc 161
#define Wc 161
#define HWc (Hc*Wc)            // 25921
#define NTOK (Bc*HWc)          // 103684
#define nHw 41
#define nWw 11
#define NWIN (Bc*nHw*nWw)      // 1804
#define NHh 8
#define NTOKP (NWIN*64)        // 115456

// ---------------- scratch ----------------
__device__ float g_xh[(size_t)NTOK*Cc];
__device__ __half g_qkv[(size_t)NTOKP*1152];
__device__ __half g_act[(size_t)NTOKP*Cc];
__device__ __half g_ot[(size_t)NTOK*Cc];
__device__ __half g_h[(size_t)NTOK*2*Cc];
__device__ __half g_wq[1152*384];
__device__ __half g_wp[384*384];
__device__ __half g_w1[768*384];
__device__ __half g_w2[384*768];
__device__ float g_bns[2688];
__device__ float g_bnt[2688];

__device__ __forceinline__ uint32_t smem_u32(const void* p) {
    uint32_t a;
    asm("{ .reg .u64 t; cvta.to.shared.u64 t, %1; cvt.u32.u64 %0, t; }" : "=r"(a) : "l"(p));
    return a;
}

// ---------------- BN prep ----------------
__global__ void bn_prep_kernel(const float* __restrict__ p, int n,
                               float* __restrict__ s, float* __restrict__ t) {
    int i = blockIdx.x * blockDim.x + threadIdx.x;
    if (i < n) {
        float g = p[i], b = p[n + i], rm = p[2*n + i], rv = p[3*n + i];
        float sc = g * rsqrtf(rv + 1e-3f);
        s[i] = sc;
        t[i] = b - rm * sc;
    }
}

// ---------------- weight convert ----------------
__global__ void wconv_kernel(const float* __restrict__ w, int n, __half* __restrict__ wh) {
    int i = blockIdx.x * blockDim.x + threadIdx.x;
    if (i < n) wh[i] = __float2half_rn(w[i]);
}

// ---------------- fused transpose + LN1 + window ----------------
// Reads x (B,C,H,W) coalesced; writes raw xh (tok-major fp32) + LN'd windowed act fp16.
__global__ void __launch_bounds__(256) tp_ln1_kernel(
    const float* __restrict__ x, const float* __restrict__ g,
    const float* __restrict__ bb, float* __restrict__ xh, __half* __restrict__ act) {
    extern __shared__ float t[];   // [384][33]
    const int b = blockIdx.y, s0 = blockIdx.x * 32;
    const int tid = threadIdx.x, lane = tid & 31, wrp = tid >> 5;

    for (int c = wrp; c < Cc; c += 8) {
        int s = s0 + lane;
        t[c * 33 + lane] = (s < HWc) ? x[((size_t)b * Cc + c) * HWc + s] : 0.f;
    }
    __syncthreads();

    #pragma unroll
    for (int jj = 0; jj < 4; jj++) {
        int j = wrp * 4 + jj;
        int s = s0 + j;
        if (s >= HWc) continue;
        float v[12];
        float sum = 0.f, sq = 0.f;
        #pragma unroll
        for (int i = 0; i < 12; i++) {
            v[i] = t[(lane + 32 * i) * 33 + j];
            sum += v[i];
            sq  += v[i] * v[i];
        }
        #pragma unroll
        for (int o = 16; o; o >>= 1) {
            sum += __shfl_xor_sync(0xffffffffu, sum, o);
            sq  += __shfl_xor_sync(0xffffffffu, sq,  o);
        }
        float mu = sum * (1.f / Cc);
        float var = sq * (1.f / Cc) - mu * mu;
        float inv = rsqrtf(var + 1e-5f);

        int hp = s / Wc, wp = s - hp * Wc;
        int widx = ((b * nHw + (hp >> 2)) * nWw + (wp >> 4)) * 64 + (hp & 3) * 16 + (wp & 15);
        size_t xbase = (size_t)(b * HWc + s) * Cc;
        size_t abase = (size_t)widx * Cc;
        #pragma unroll
        for (int i = 0; i < 12; i++) {
            int c = lane + 32 * i;
            xh[xbase + c] = v[i];
            act[abase + c] = __float2half_rn((v[i] - mu) * inv * g[c] + bb[c]);
        }
    }
}

// zero pad rows of act
__global__ void pad_fill_kernel(__half* __restrict__ act) {
    int tokw = blockIdx.x * blockDim.x + threadIdx.x;
    if (tokw >= NTOKP) return;
    int wi = tokw >> 6, l = tokw & 63;
    int r = wi % (nHw * nWw);
    int hwi = r / nWw, wwi = r % nWw;
    int hp = hwi * 4 + (l >> 4), wp = wwi * 16 + (l & 15);
    if (hp < Hc && wp < Wc) return;
    uint4* dst = (uint4*)(act + (size_t)tokw * Cc);
    uint4 z = make_uint4(0, 0, 0, 0);
    #pragma unroll
    for (int i = 0; i < 48; i++) dst[i] = z;
}

// ---------------- transpose out ----------------
__global__ void transpose_out_kernel(const float* __restrict__ xh, float* __restrict__ out) {
    __shared__ float tile[32][33];
    int b = blockIdx.z, c0 = blockIdx.y * 32, s0 = blockIdx.x * 32;
    int tx = threadIdx.x, ty = threadIdx.y;
    #pragma unroll
    for (int r = 0; r < 32; r += 8) {
        int s = s0 + ty + r, c = c0 + tx;
        if (s < HWc) tile[ty + r][tx] = xh[((size_t)b * HWc + s) * Cc + c];
    }
    __syncthreads();
    #pragma unroll
    for (int r = 0; r < 32; r += 8) {
        int s = s0 + tx, c = c0 + ty + r;
        if (s < HWc) out[((size_t)b * Cc + c) * HWc + s] = tile[tx][ty + r];
    }
}

// ---------------- LN2 ----------------
__device__ __forceinline__ void ln_block_reduce(float& s, float& q, float* sm) {
    #pragma unroll
    for (int o = 16; o; o >>= 1) {
        s += __shfl_down_sync(0xffffffffu, s, o);
        q += __shfl_down_sync(0xffffffffu, q, o);
    }
    int w = threadIdx.x >> 5, lane = threadIdx.x & 31;
    if (!lane) { sm[w] = s; sm[4 + w] = q; }
    __syncthreads();
    s = sm[0] + sm[1] + sm[2] + sm[3];
    q = sm[4] + sm[5] + sm[6] + sm[7];
}

__global__ void __launch_bounds__(128) ln2_kernel(
    const float* __restrict__ xh, const float* __restrict__ g,
    const float* __restrict__ bb, __half* __restrict__ oh) {
    __shared__ float sm[8];
    int tok = blockIdx.x;
    int tid = threadIdx.x;
    const float* row = xh + (size_t)tok * Cc;
    size_t obase = (size_t)tok * Cc;
    float v0 = row[tid], v1 = row[tid + 128], v2 = row[tid + 256];
    float s = v0 + v1 + v2;
    float q = v0*v0 + v1*v1 + v2*v2;
    ln_block_reduce(s, q, sm);
    float mu = s * (1.f / Cc);
    float var = q * (1.f / Cc) - mu * mu;
    float inv = rsqrtf(var + 1e-5f);
    oh[obase + tid]       = __float2half_rn((v0 - mu) * inv * g[tid]       + bb[tid]);
    oh[obase + tid + 128] = __float2half_rn((v1 - mu) * inv * g[tid + 128] + bb[tid + 128]);
    oh[obase + tid + 256] = __float2half_rn((v2 - mu) * inv * g[tid + 256] + bb[tid + 256]);
}

// ============================================================================
// fp16 tensor-core GEMM (unchanged from R5)
// ============================================================================
#define PAD 40
#define A_ELE (128*PAD)
#define W_ELE (64*PAD)
#define STG_ELE (A_ELE + W_ELE)
#define GEMM_SMEM_B (3 * STG_ELE * 2)

__device__ __forceinline__ void ldm_x4(uint32_t* r, uint32_t addr) {
    asm volatile("ldmatrix.sync.aligned.m8n8.x4.shared.b16 {%0,%1,%2,%3}, [%4];"
        : "=r"(r[0]), "=r"(r[1]), "=r"(r[2]), "=r"(r[3]) : "r"(addr));
}
__device__ __forceinline__ void ldm_x4_trans(uint32_t* r, uint32_t addr) {
    asm volatile("ldmatrix.sync.aligned.m8n8.x4.trans.shared.b16 {%0,%1,%2,%3}, [%4];"
        : "=r"(r[0]), "=r"(r[1]), "=r"(r[2]), "=r"(r[3]) : "r"(addr));
}
__device__ __forceinline__ void mma_f16(float* c, const uint32_t* a, const uint32_t* b) {
    asm volatile("mma.sync.aligned.m16n8k16.row.col.f32.f16.f16.f32 "
        "{%0,%1,%2,%3}, {%4,%5,%6,%7}, {%8,%9}, {%0,%1,%2,%3};"
        : "+f"(c[0]), "+f"(c[1]), "+f"(c[2]), "+f"(c[3])
        : "r"(a[0]), "r"(a[1]), "r"(a[2]), "r"(a[3]), "r"(b[0]), "r"(b[1]));
}
#define CP16(dst, src, sz) \
    asm volatile("cp.async.cg.shared.global [%0], [%1], 16, %2;" :: "r"(dst), "l"(src), "r"(sz))
#define CP_COMMIT() asm volatile("cp.async.commit_group;" ::: "memory")
#define CP_WAIT1()  asm volatile("cp.async.wait_group 1;" ::: "memory")
#define CP_WAIT0()  asm volatile("cp.async.wait_group 0;" ::: "memory")

template<int EPI>
__global__ void __launch_bounds__(256, 2) gemm_f16_kernel(
    const __half* __restrict__ A, const __half* __restrict__ W,
    const float* __restrict__ bns, const float* __restrict__ bnt,
    const float* __restrict__ resid, float* __restrict__ Cf,
    __half* __restrict__ Ch,
    int M, int N, int K) {
    extern __shared__ __align__(16) __half smem[];
    const int tid = threadIdx.x;
    const int wid = tid >> 5, lane = tid & 31;
    const int m0 = blockIdx.y * 128, n0 = blockIdx.x * 64;
    const int m_off = (wid & 3) * 32, n_off = (wid >> 2) * 32;
    const int nk = K >> 5;

    const int lrow = tid >> 2, lgrp = (tid & 3) * 8;

    float acc[2][4][4];
    #pragma unroll
    for (int i = 0; i < 2; i++)
        #pragma unroll
        for (int j = 0; j < 4; j++)
            #pragma unroll
            for (int e = 0; e < 4; e++) acc[i][j][e] = 0.f;

    auto issue = [&](int k0, int st) {
        __half* base = smem + st * STG_ELE;
        #pragma unroll
        for (int it = 0; it < 2; it++) {
            int r = lrow + it * 64;
            int gm = m0 + r;
            int ok = (gm < M);
            const __half* src = A + (size_t)(ok ? gm : 0) * K + k0 + lgrp;
            CP16(smem_u32(base + r * PAD + lgrp), src, ok ? 16 : 0);
        }
        {
            const __half* src = W + (size_t)(n0 + lrow) * K + k0 + lgrp;
            CP16(smem_u32(base + A_ELE + lrow * PAD + lgrp), src, 16);
        }
    };

    issue(0, 0);  CP_COMMIT();
    issue(32, 1); CP_COMMIT();

    const int frow = lane & 15, fsel = (lane >> 4) * 8;

    for (int k = 0; k < nk; k++) {
        CP_WAIT1();
        __syncthreads();
        if (k + 2 < nk) issue((k + 2) * 32, (k + 2) % 3);
        CP_COMMIT();

        const __half* sA = smem + (k % 3) * STG_ELE;
        const __half* sW = sA + A_ELE;

        #pragma unroll
        for (int ks = 0; ks < 2; ks++) {
            const int kc = ks * 16 + fsel;
            uint32_t af[2][4], bf[4][2];
            #pragma unroll
            for (int mt = 0; mt < 2; mt++)
                ldm_x4(af[mt], smem_u32(sA + (m_off + mt*16 + frow) * PAD + kc));
            #pragma unroll
            for (int np = 0; np < 2; np++) {
                uint32_t r[4];
                ldm_x4(r, smem_u32(sW + (n_off + np*16 + frow) * PAD + kc));
                bf[2*np][0] = r[0]; bf[2*np][1] = r[2];
                bf[2*np+1][0] = r[1]; bf[2*np+1][1] = r[3];
            }
            #pragma unroll
            for (int mt = 0; mt < 2; mt++)
                #pragma unroll
                for (int nt = 0; nt < 4; nt++)
                    mma_f16(acc[mt][nt], af[mt], bf[nt]);
        }
        __syncthreads();
    }

    const int erow = lane >> 2, ecol = (lane & 3) * 2;
    #pragma unroll
    for (int mt = 0; mt < 2; mt++) {
        #pragma unroll
        for (int half = 0; half < 2; half++) {
            int m = m0 + m_off + mt * 16 + erow + half * 8;
            if (m < M) {
                size_t rowoff = (size_t)m * N;
                #pragma unroll
                for (int nt = 0; nt < 4; nt++) {
                    int n = n0 + n_off + nt * 8 + ecol;
                    float v0 = acc[mt][nt][half*2]     * bns[n]     + bnt[n];
                    float v1 = acc[mt][nt][half*2 + 1] * bns[n + 1] + bnt[n + 1];
                    if (EPI == 2) {
                        v0 = v0 / (1.f + __expf(-v0));
                        v1 = v1 / (1.f + __expf(-v1));
                    }
                    if (EPI == 1) {
                        float2 rr = *(const float2*)(resid + rowoff + n);
                        v0 += rr.x; v1 += rr.y;
                        *(float2*)(Cf + rowoff + n) = make_float2(v0, v1);
                    } else {
                        __half2 hv = __floats2half2_rn(v0, v1);
                        *(__half2*)(Ch + rowoff + n) = hv;
                    }
                }
            }
        }
    }
}

// ============================================================================
// Tensor-core attention: CTA per (window, head), 4 warps.
// Warp w computes S strip rows [w*16, w*16+16) of 64x64, softmax in regs,
// P@V via C-frag -> A-frag identity, V loaded with ldmatrix.trans.
// ============================================================================
#define APAD 56

__global__ void __launch_bounds__(128) attn_mma_kernel(
    const __half* __restrict__ qkv, __half* __restrict__ ot) {
    __shared__ __half sQ[64][APAD];
    __shared__ __half sK[64][APAD];
    __shared__ __half sV[64][APAD];
    const int blk = blockIdx.x;
    const int win = blk >> 3, h = blk & 7;
    const int tid = threadIdx.x;
    const int wid = tid >> 5, lane = tid & 31;
    const float scale = 0.144337567297406f;  // 1/sqrt(48)

    // load q/k/v rows for this head: 192 rows x 96B
    const size_t base = (size_t)win * 64 * 1152 + h * 48;
    #pragma unroll
    for (int it = 0; it < 2; it++) {
        int r = tid + it * 128;
        if (r < 192) {
            int mat = r >> 6, l = r & 63;
            const __half* src = qkv + base + (size_t)l * 1152 + mat * 384;
            __half* dst = (mat == 0) ? sQ[l] : (mat == 1) ? sK[l] : sV[l];
            #pragma unroll
            for (int c = 0; c < 6; c++)
                CP16(smem_u32(dst + c * 8), src + c * 8, 16);
        }
    }
    CP_COMMIT();
    CP_WAIT0();
    __syncthreads();

    const int m0 = wid * 16;
    const int frow = lane & 15, fsel = (lane >> 4) * 8;

    // S = Q @ K^T : 8 n-tiles x fp32
    float s[8][4];
    #pragma unroll
    for (int i = 0; i < 8; i++)
        #pragma unroll
        for (int e = 0; e < 4; e++) s[i][e] = 0.f;

    #pragma unroll
    for (int kci = 0; kci < 3; kci++) {
        const int kc = kci * 16;
        uint32_t a[4], b[8][2];
        ldm_x4(a, smem_u32(&sQ[m0 + frow][kc + fsel]));
        #pragma unroll
        for (int np = 0; np < 4; np++) {
            uint32_t r[4];
            ldm_x4(r, smem_u32(&sK[np * 16 + frow][kc + fsel]));
            b[2*np][0] = r[0]; b[2*np][1] = r[2];
            b[2*np+1][0] = r[1]; b[2*np+1][1] = r[3];
        }
        #pragma unroll
        for (int nt = 0; nt < 8; nt++)
            mma_f16(s[nt], a, b[nt]);
    }

    // softmax (rows r0 = lane>>2, r1 = r0+8 of the strip)
    float mx0 = -1e30f, mx1 = -1e30f;
    #pragma unroll
    for (int nt = 0; nt < 8; nt++) {
        #pragma unroll
        for (int e = 0; e < 4; e++) s[nt][e] *= scale;
        mx0 = fmaxf(mx0, fmaxf(s[nt][0], s[nt][1]));
        mx1 = fmaxf(mx1, fmaxf(s[nt][2], s[nt][3]));
    }
    #pragma unroll
    for (int o = 1; o <= 2; o <<= 1) {
        mx0 = fmaxf(mx0, __shfl_xor_sync(0xffffffffu, mx0, o));
        mx1 = fmaxf(mx1, __shfl_xor_sync(0xffffffffu, mx1, o));
    }
    float sm0 = 0.f, sm1 = 0.f;
    #pragma unroll
    for (int nt = 0; nt < 8; nt++) {
        s[nt][0] = __expf(s[nt][0] - mx0);
        s[nt][1] = __expf(s[nt][1] - mx0);
        s[nt][2] = __expf(s[nt][2] - mx1);
        s[nt][3] = __expf(s[nt][3] - mx1);
        sm0 += s[nt][0] + s[nt][1];
        sm1 += s[nt][2] + s[nt][3];
    }
    #pragma unroll
    for (int o = 1; o <= 2; o <<= 1) {
        sm0 += __shfl_xor_sync(0xffffffffu, sm0, o);
        sm1 += __shfl_xor_sync(0xffffffffu, sm1, o);
    }
    const float inv0 = 1.f / sm0, inv1 = 1.f / sm1;

    // P frags: k-chunk j combines s tiles 2j, 2j+1
    uint32_t pa[4][4];
    #pragma unroll
    for (int j = 0; j < 4; j++) {
        __half2 h0 = __floats2half2_rn(s[2*j][0],   s[2*j][1]);
        __half2 h1 = __floats2half2_rn(s[2*j][2],   s[2*j][3]);
        __half2 h2v = __floats2half2_rn(s[2*j+1][0], s[2*j+1][1]);
        __half2 h3 = __floats2half2_rn(s[2*j+1][2], s[2*j+1][3]);
        pa[j][0] = *(uint32_t*)&h0;
        pa[j][1] = *(uint32_t*)&h1;
        pa[j][2] = *(uint32_t*)&h2v;
        pa[j][3] = *(uint32_t*)&h3;
    }

    // O = P @ V : 6 n-tiles (48 dims), k = 64 tokens
    float o[6][4];
    #pragma unroll
    for (int i = 0; i < 6; i++)
        #pragma unroll
        for (int e = 0; e < 4; e++) o[i][e] = 0.f;

    #pragma unroll
    for (int kc4 = 0; kc4 < 4; kc4++) {
        uint32_t bv[6][2];
        #pragma unroll
        for (int nb = 0; nb < 3; nb++) {
            uint32_t r[4];
            ldm_x4_trans(r, smem_u32(&sV[kc4 * 16 + frow][nb * 16 + fsel]));
            bv[2*nb][0]   = r[0]; bv[2*nb][1]   = r[1];
            bv[2*nb+1][0] = r[2]; bv[2*nb+1][1] = r[3];
        }
        #pragma unroll
        for (int nt = 0; nt < 6; nt++)
            mma_f16(o[nt], pa[kc4], bv[nt]);
    }

    // store: normalize rows, scatter window -> token layout
    const int b  = win / (nHw * nWw);
    const int r2 = win % (nHw * nWw);
    const int hwi = r2 / nWw, wwi = r2 % nWw;
    const int l0 = m0 + (lane >> 2), l1 = l0 + 8;
    const int ecol = (lane & 3) * 2;

    int hp0 = hwi * 4 + (l0 >> 4), wp0 = wwi * 16 + (l0 & 15);
    int hp1 = hwi * 4 + (l1 >> 4), wp1 = wwi * 16 + (l1 & 15);
    bool ok0 = (hp0 < Hc) && (wp0 < Wc);
    bool ok1 = (hp1 < Hc) && (wp1 < Wc);
    size_t row0 = ok0 ? (((size_t)(b * Hc + hp0) * Wc + wp0) * Cc + h * 48) : 0;
    size_t row1 = ok1 ? (((size_t)(b * Hc + hp1) * Wc + wp1) * Cc + h * 48) : 0;

    #pragma unroll
    for (int nt = 0; nt < 6; nt++) {
        int n = nt * 8 + ecol;
        if (ok0) {
            __half2 hv = __floats2half2_rn(o[nt][0] * inv0, o[nt][1] * inv0);
            *(__half2*)(ot + row0 + n) = hv;
        }
        if (ok1) {
            __half2 hv = __floats2half2_rn(o[nt][2] * inv1, o[nt][3] * inv1);
            *(__half2*)(ot + row1 + n) = hv;
        }
    }
}

// ---------------- host ----------------
#define TPLN1_SMEM (384*33*4)

extern "C" void kernel_launch(void* const* d_in, const int* in_sizes, int n_in,
                              void* d_out, int out_size) {
    const float* x       = (const float*)d_in[0];
    const float* qkv_w   = (const float*)d_in[1];
    const float* qkv_bn  = (const float*)d_in[2];
    const float* proj_w  = (const float*)d_in[3];
    const float* proj_bn = (const float*)d_in[4];
    const float* n1_g    = (const float*)d_in[5];
    const float* n1_b    = (const float*)d_in[6];
    const float* n2_g    = (const float*)d_in[7];
    const float* n2_b    = (const float*)d_in[8];
    const float* mlp1_w  = (const float*)d_in[9];
    const float* mlp1_bn = (const float*)d_in[10];
    const float* mlp2_w  = (const float*)d_in[11];
    const float* mlp2_bn = (const float*)d_in[12];
    float* out = (float*)d_out;

    float *xh, *bns, *bnt;
    __half *qkv, *act, *ot, *hbuf, *wq, *wp, *w1, *w2;
    cudaGetSymbolAddress((void**)&xh,   g_xh);
    cudaGetSymbolAddress((void**)&qkv,  g_qkv);
    cudaGetSymbolAddress((void**)&bns,  g_bns);
    cudaGetSymbolAddress((void**)&bnt,  g_bnt);
    cudaGetSymbolAddress((void**)&act,  g_act);
    cudaGetSymbolAddress((void**)&ot,   g_ot);
    cudaGetSymbolAddress((void**)&hbuf, g_h);
    cudaGetSymbolAddress((void**)&wq,   g_wq);
    cudaGetSymbolAddress((void**)&wp,   g_wp);
    cudaGetSymbolAddress((void**)&w1,   g_w1);
    cudaGetSymbolAddress((void**)&w2,   g_w2);

    cudaFuncSetAttribute(gemm_f16_kernel<0>, cudaFuncAttributeMaxDynamicSharedMemorySize, GEMM_SMEM_B);
    cudaFuncSetAttribute(gemm_f16_kernel<1>, cudaFuncAttributeMaxDynamicSharedMemorySize, GEMM_SMEM_B);
    cudaFuncSetAttribute(gemm_f16_kernel<2>, cudaFuncAttributeMaxDynamicSharedMemorySize, GEMM_SMEM_B);
    cudaFuncSetAttribute(tp_ln1_kernel, cudaFuncAttributeMaxDynamicSharedMemorySize, TPLN1_SMEM);

    bn_prep_kernel<<<5, 256>>>(qkv_bn, 1152, bns + 0,    bnt + 0);
    bn_prep_kernel<<<2, 256>>>(proj_bn, 384, bns + 1152, bnt + 1152);
    bn_prep_kernel<<<3, 256>>>(mlp1_bn, 768, bns + 1536, bnt + 1536);
    bn_prep_kernel<<<2, 256>>>(mlp2_bn, 384, bns + 2304, bnt + 2304);

    wconv_kernel<<<(442368 + 255)/256, 256>>>(qkv_w,  442368, wq);
    wconv_kernel<<<(147456 + 255)/256, 256>>>(proj_w, 147456, wp);
    wconv_kernel<<<(294912 + 255)/256, 256>>>(mlp1_w, 294912, w1);
    wconv_kernel<<<(294912 + 255)/256, 256>>>(mlp2_w, 294912, w2);

    pad_fill_kernel<<<(NTOKP + 255)/256, 256>>>(act);
    tp_ln1_kernel<<<dim3(811, Bc), 256, TPLN1_SMEM>>>(x, n1_g, n1_b, xh, act);

    // qkv = BN(win @ qkv_w^T) -> fp16
    gemm_f16_kernel<0><<<dim3(18, 902), 256, GEMM_SMEM_B>>>(
        act, wq, bns, bnt, nullptr, nullptr, qkv, NTOKP, 1152, Cc);

    attn_mma_kernel<<<NWIN * NHh, 128>>>(qkv, ot);

    // xh += BN(ot @ proj_w^T)
    gemm_f16_kernel<1><<<dim3(6, 811), 256, GEMM_SMEM_B>>>(
        ot, wp, bns + 1152, bnt + 1152, xh, xh, nullptr, NTOK, Cc, Cc);

    ln2_kernel<<<NTOK, 128>>>(xh, n2_g, n2_b, act);

    // h = silu(BN(xn2 @ mlp1_w^T)) -> fp16
    gemm_f16_kernel<2><<<dim3(12, 811), 256, GEMM_SMEM_B>>>(
        act, w1, bns + 1536, bnt + 1536, nullptr, nullptr, hbuf, NTOK, 2 * Cc, Cc);

    // xh += BN(h @ mlp2_w^T)
    gemm_f16_kernel<1><<<dim3(6, 811), 256, GEMM_SMEM_B>>>(
        hbuf, w2, bns + 2304, bnt + 2304, xh, xh, nullptr, NTOK, Cc, 2 * Cc);

    transpose_out_kernel<<<dim3(811, 12, Bc), dim3(32, 8)>>>(xh, out);
}